// round 7
// baseline (speedup 1.0000x reference)
#include <cuda_runtime.h>
#include <cstdint>
#include <math.h>

// Problem dims
#define NB 8
#define NH 8
#define SLQ 1024
#define SLK 1024
#define DD 512
#define HD 4096

// ---------------- device global scratch ----------------
// int8 two-digit planes
__device__ int8_t g_x1[(size_t)NB*SLQ*DD],  g_x2[(size_t)NB*SLQ*DD];
__device__ int8_t g_st1[(size_t)NB*SLK*DD], g_st2[(size_t)NB*SLK*DD];
__device__ int8_t g_wq1[(size_t)NH*DD*DD],  g_wq2[(size_t)NH*DD*DD];
__device__ int8_t g_wk1[(size_t)NH*DD*DD],  g_wk2[(size_t)NH*DD*DD];
__device__ int8_t g_wv1[(size_t)NH*DD*DD],  g_wv2[(size_t)NH*DD*DD];
__device__ int8_t g_wp1[(size_t)DD*HD],     g_wp2[(size_t)DD*HD];
__device__ int8_t g_qk1[(size_t)128*SLQ*DD], g_qk2[(size_t)128*SLQ*DD]; // Q: z<64, K: z>=64
__device__ int8_t g_vt1[(size_t)64*DD*SLK],  g_vt2[(size_t)64*DD*SLK];
__device__ int8_t g_p1[(size_t)64*SLQ*SLK],  g_p2[(size_t)64*SLQ*SLK];
__device__ int8_t g_c1[(size_t)NB*SLQ*HD],   g_c2[(size_t)NB*SLQ*HD];
__device__ float  g_S[(size_t)64*SLQ*SLK];      // masked scaled scores (fp32)
__device__ float  g_ctx[(size_t)NB*SLQ*HD];     // ctx fp32 (pre-quant)
__device__ float  g_psc[(size_t)64*SLQ];        // per-row P scale (= 1/sum)
__device__ float  g_csc[(size_t)NB*SLQ];        // per-row ctx absmax

// ---------------- PTX helpers (baseline ISA only) ----------------
__device__ __forceinline__ uint32_t smem_u32(const void* p) {
    uint32_t a;
    asm("{ .reg .u64 t; cvta.to.shared.u64 t, %1; cvt.u32.u64 %0, t; }" : "=r"(a) : "l"(p));
    return a;
}
#define CP_ASYNC16(dst, src) \
    asm volatile("cp.async.cg.shared.global [%0], [%1], 16;" :: "r"(dst), "l"(src))
#define CP_COMMIT() asm volatile("cp.async.commit_group;" ::: "memory")
#define CP_WAIT1() asm volatile("cp.async.wait_group 1;" ::: "memory")
#define CP_WAIT0() asm volatile("cp.async.wait_group 0;" ::: "memory")

__device__ __forceinline__ void ldsm_x4(uint32_t* r, uint32_t addr) {
    asm volatile("ldmatrix.sync.aligned.m8n8.x4.shared.b16 {%0,%1,%2,%3}, [%4];"
        : "=r"(r[0]), "=r"(r[1]), "=r"(r[2]), "=r"(r[3]) : "r"(addr));
}
__device__ __forceinline__ void mmai8(int* d, const uint32_t* a, const uint32_t* b) {
    asm volatile("mma.sync.aligned.m16n8k32.row.col.s32.s8.s8.s32 "
        "{%0,%1,%2,%3}, {%4,%5,%6,%7}, {%8,%9}, {%0,%1,%2,%3};"
        : "+r"(d[0]), "+r"(d[1]), "+r"(d[2]), "+r"(d[3])
        : "r"(a[0]), "r"(a[1]), "r"(a[2]), "r"(a[3]), "r"(b[0]), "r"(b[1]));
}

// block-linear layout for 128-row x 64B(K) tiles: each 8x16B matrix contiguous 128B
__device__ __forceinline__ uint32_t blin(int row, int c16) {
    return (uint32_t)(c16 * 2048 + ((row >> 3) << 7) + ((row & 7) << 4));
}

// two-digit int8 quantization: x ~= (s/127)*(q1 + q2/256), inv127 = 127/s
__device__ __forceinline__ void quant2f(float x, float inv127, int8_t& a, int8_t& b) {
    float t = x * inv127;
    float r1 = fminf(fmaxf(rintf(t), -127.f), 127.f);
    float r2 = fminf(fmaxf(rintf((t - r1) * 256.f), -127.f), 127.f);
    a = (int8_t)(int)r1;
    b = (int8_t)(int)r2;
}

// Tiles: CTA 128(M) x 128(N) x 64(K int8); 8 warps in 2(M)x4(N), warp tile 64x32.
// Stage (32KB): A1 8K | A2 8K | B1 8K | B2 8K. 2 stages = 64KB.
#define PLANE_B 8192
#define STAGE_B 32768
#define GEMM_SMEM 65536

// Epilogue IDs
#define EPI_QK  0  // dual-source, bias + quantize, row-major int8 planes
#define EPI_VT  1  // bias + quantize, transposed int8 planes (V^T)
#define EPI_SC  2  // (already scaled) + mask -> fp32
#define EPI_CTX 3  // rowsc dequant -> fp32 (head-concat)
#define EPI_OUT 4  // rowsc dequant + bias -> fp32

#define INV127_OUT 18.142857142857142f  // 127/7 for Q/K/V quantization

template<int EPI>
__global__ void __launch_bounds__(256, 1) igemm(
    const int8_t* __restrict__ A1, const int8_t* __restrict__ A2,
    const int8_t* __restrict__ A1b, const int8_t* __restrict__ A2b, int lda,
    const int8_t* __restrict__ B1, const int8_t* __restrict__ B2,
    const int8_t* __restrict__ B1b, const int8_t* __restrict__ B2b, int ldb,
    int Ktot, float ab, const float* __restrict__ rowsc,
    const float* __restrict__ bias, const float* __restrict__ bias2,
    const int* __restrict__ mask,
    float* __restrict__ outf,
    int8_t* __restrict__ oq1, int8_t* __restrict__ oq2, int ldo)
{
    extern __shared__ char smem[];
    const uint32_t sb = smem_u32(smem);
    const int tid = threadIdx.x;
    const int wid = tid >> 5;
    const int lane = tid & 31;
    const int z = blockIdx.z;
    const int m0 = blockIdx.y * 128;
    const int n0 = blockIdx.x * 128;

    size_t aOff = 0, bOff = 0, oOff = 0, mOff = 0, rsOff = 0;
    if (EPI == EPI_QK) {
        const int zz = z & 63;
        if (z >= 64) { A1 = A1b; A2 = A2b; B1 = B1b; B2 = B2b; bias = bias2; }
        aOff = (size_t)(zz >> 3) * SLQ * DD;
        bOff = (size_t)(zz & 7) * DD * DD;
        oOff = (size_t)z * SLQ * DD;
    } else if (EPI == EPI_VT) {
        aOff = (size_t)(z >> 3) * SLQ * DD;
        bOff = (size_t)(z & 7) * DD * DD;
        oOff = (size_t)z * DD * SLK;
    } else if (EPI == EPI_SC) {
        aOff = (size_t)z * SLQ * DD;
        bOff = (size_t)z * SLK * DD;
        oOff = (size_t)z * SLQ * SLK;
        mOff = (size_t)(z >> 3) * SLQ * SLK;
    } else if (EPI == EPI_CTX) {
        aOff = (size_t)z * SLQ * SLK;
        bOff = (size_t)z * DD * SLK;
        oOff = (size_t)(z >> 3) * SLQ * HD + (size_t)(z & 7) * DD;
        rsOff = (size_t)z * SLQ;
    }

    // ---- loader mapping: 4 planes x 64 threads; 8 x 16B per thread per chunk
    const int plane = tid >> 6;
    const int t64 = tid & 63;
    const int c16 = t64 & 3;
    const int rb = t64 >> 2;  // rows rb + 16i
    const int8_t* srcT;
    int ldT;
    if (plane == 0)      { srcT = A1 + aOff + (size_t)m0 * lda; ldT = lda; }
    else if (plane == 1) { srcT = A2 + aOff + (size_t)m0 * lda; ldT = lda; }
    else if (plane == 2) { srcT = B1 + bOff + (size_t)n0 * ldb; ldT = ldb; }
    else                 { srcT = B2 + bOff + (size_t)n0 * ldb; ldT = ldb; }
    srcT += (size_t)rb * ldT + c16 * 16;

    uint32_t dstoff[8];
    #pragma unroll
    for (int i = 0; i < 8; i++)
        dstoff[i] = blin(rb + 16 * i, c16);
    const uint32_t pbase0 = sb + plane * PLANE_B;

    const int NCH = Ktot >> 6;  // BK = 64 int8

#define LOAD_CHUNK(stg, kt) do { \
    const uint32_t _b = pbase0 + (stg) * STAGE_B; \
    _Pragma("unroll") \
    for (int i = 0; i < 8; i++) CP_ASYNC16(_b + dstoff[i], srcT + (kt) + (size_t)(16 * i) * ldT); \
    CP_COMMIT(); } while (0)

    LOAD_CHUNK(0, 0);

    // ---- compute mapping: warp grid 2(M) x 4(N), warp tile 64x32
    const int warpM = wid >> 2;
    const int warpN = wid & 3;
    const int grp = lane >> 3;
    const int l7 = lane & 7;
    const int arowb = warpM * 64 + ((grp & 1) << 3) + l7;  // + mt*16
    const int akc   = grp >> 1;                             // + 2*ks
    const int browb = warpN * 32 + ((grp >> 1) << 3) + l7; // + p*16
    const int bkc   = grp & 1;                              // + 2*ks

    int hi[4][4][4], mid[4][4][4];
    #pragma unroll
    for (int mt = 0; mt < 4; mt++)
        #pragma unroll
        for (int nt = 0; nt < 4; nt++)
            #pragma unroll
            for (int j = 0; j < 4; j++) { hi[mt][nt][j] = 0; mid[mt][nt][j] = 0; }

    for (int c = 0; c < NCH; c++) {
        if (c + 1 < NCH) {
            LOAD_CHUNK((c + 1) & 1, (size_t)(c + 1) * 64);
            CP_WAIT1();
        } else {
            CP_WAIT0();
        }
        __syncthreads();

        const uint32_t st = sb + (c & 1) * STAGE_B;
        #pragma unroll
        for (int ks = 0; ks < 2; ks++) {
            uint32_t a1[4][4], a2[4][4];
            #pragma unroll
            for (int mt = 0; mt < 4; mt++) {
                const uint32_t off = blin(arowb + mt * 16, akc + 2 * ks);
                ldsm_x4(a1[mt], st + off);
                ldsm_x4(a2[mt], st + PLANE_B + off);
            }
            #pragma unroll
            for (int p = 0; p < 2; p++) {
                uint32_t b1[4], b2[4];
                const uint32_t off = blin(browb + p * 16, bkc + 2 * ks);
                ldsm_x4(b1, st + 2 * PLANE_B + off);
                ldsm_x4(b2, st + 3 * PLANE_B + off);
                #pragma unroll
                for (int mt = 0; mt < 4; mt++) {
                    #pragma unroll
                    for (int h = 0; h < 2; h++) {
                        const int nt = p * 2 + h;
                        mmai8(hi[mt][nt],  a1[mt], &b1[h * 2]);
                        mmai8(mid[mt][nt], a1[mt], &b2[h * 2]);
                        mmai8(mid[mt][nt], a2[mt], &b1[h * 2]);
                    }
                }
            }
        }
        __syncthreads();
    }

    // ---------------- epilogue ----------------
    const int r4 = lane >> 2;
    const int c2 = (lane & 3) * 2;
    const int colb = n0 + warpN * 32 + c2;

    #pragma unroll
    for (int mt = 0; mt < 4; mt++) {
        #pragma unroll
        for (int rh = 0; rh < 2; rh++) {
            const int row = m0 + warpM * 64 + mt * 16 + rh * 8 + r4;
            float scl = ab;
            if (EPI == EPI_CTX) scl *= rowsc[rsOff + row];
            if (EPI == EPI_OUT) scl *= rowsc[row];
            #pragma unroll
            for (int nt = 0; nt < 4; nt++) {
                const int col = colb + nt * 8;
                const int j = rh * 2;
                float v0 = scl * ((float)hi[mt][nt][j]     + 0.00390625f * (float)mid[mt][nt][j]);
                float v1 = scl * ((float)hi[mt][nt][j + 1] + 0.00390625f * (float)mid[mt][nt][j + 1]);
                if (EPI == EPI_QK) {
                    v0 += bias[col]; v1 += bias[col + 1];
                    char2 p1, p2;
                    quant2f(v0, INV127_OUT, ((int8_t*)&p1)[0], ((int8_t*)&p2)[0]);
                    quant2f(v1, INV127_OUT, ((int8_t*)&p1)[1], ((int8_t*)&p2)[1]);
                    const size_t o = oOff + (size_t)row * ldo + col;
                    *(char2*)(oq1 + o) = p1;
                    *(char2*)(oq2 + o) = p2;
                } else if (EPI == EPI_VT) {
                    v0 += bias[col]; v1 += bias[col + 1];
                    int8_t q1a, q2a, q1b, q2b;
                    quant2f(v0, INV127_OUT, q1a, q2a);
                    quant2f(v1, INV127_OUT, q1b, q2b);
                    const size_t o0 = oOff + (size_t)col * SLK + row;
                    oq1[o0] = q1a; oq2[o0] = q2a;
                    oq1[o0 + SLK] = q1b; oq2[o0 + SLK] = q2b;
                } else if (EPI == EPI_SC) {
                    const size_t o = oOff + (size_t)row * SLK + col;
                    int2 mk = *(const int2*)(mask + mOff + (size_t)row * SLK + col);
                    float2 ov;
                    ov.x = mk.x ? v0 : -1e30f;
                    ov.y = mk.y ? v1 : -1e30f;
                    *(float2*)(outf + o) = ov;
                } else if (EPI == EPI_CTX) {
                    float2 ov; ov.x = v0; ov.y = v1;
                    *(float2*)(outf + oOff + (size_t)row * ldo + col) = ov;
                } else {  // EPI_OUT
                    float2 ov;
                    ov.x = v0 + bias[col];
                    ov.y = v1 + bias[col + 1];
                    *(float2*)(outf + (size_t)row * ldo + col) = ov;
                }
            }
        }
    }
}

// ---------------- input quantization (fixed per-tensor scales) ----------------
__global__ void quant_in(
    const float* __restrict__ x, const float* __restrict__ st,
    const float* __restrict__ wq, const float* __restrict__ wk,
    const float* __restrict__ wv, const float* __restrict__ wp,
    int8_t* x1, int8_t* x2, int8_t* s1, int8_t* s2,
    int8_t* q1, int8_t* q2, int8_t* k1, int8_t* k2,
    int8_t* v1, int8_t* v2, int8_t* p1, int8_t* p2)
{
    const float INV_X = 127.0f / 7.0f;                     // sigma = 1
    const float INV_W = 127.0f * 22.62741699796952f / 7.0f; // sigma = 1/sqrt(512)
    const float INV_P = 127.0f * 64.0f / 7.0f;             // sigma = 1/64
    const int which = blockIdx.y;
    const float* s; int8_t *d1, *d2; int n4; float inv;
    if (which == 0)      { s = x;  d1 = x1; d2 = x2; n4 = NB*SLQ*DD/4; inv = INV_X; }
    else if (which == 1) { s = st; d1 = s1; d2 = s2; n4 = NB*SLK*DD/4; inv = INV_X; }
    else if (which == 2) { s = wq; d1 = q1; d2 = q2; n4 = NH*DD*DD/4;  inv = INV_W; }
    else if (which == 3) { s = wk; d1 = k1; d2 = k2; n4 = NH*DD*DD/4;  inv = INV_W; }
    else if (which == 4) { s = wv; d1 = v1; d2 = v2; n4 = NH*DD*DD/4;  inv = INV_W; }
    else                 { s = wp; d1 = p1; d2 = p2; n4 = DD*HD/4;     inv = INV_P; }
    int i = blockIdx.x * blockDim.x + threadIdx.x;
    if (i >= n4) return;
    float4 v = ((const float4*)s)[i];
    char4 a, b;
    quant2f(v.x, inv, ((int8_t*)&a)[0], ((int8_t*)&b)[0]);
    quant2f(v.y, inv, ((int8_t*)&a)[1], ((int8_t*)&b)[1]);
    quant2f(v.z, inv, ((int8_t*)&a)[2], ((int8_t*)&b)[2]);
    quant2f(v.w, inv, ((int8_t*)&a)[3], ((int8_t*)&b)[3]);
    ((char4*)d1)[i] = a;
    ((char4*)d2)[i] = b;
}

// ---------------- softmax + P quantization (row scale = 1/sum, free) ----------------
__global__ void __launch_bounds__(256) softmax_q()
{
    const size_t row = blockIdx.x;
    const float* p = g_S + row * SLK;
    const int tid = threadIdx.x;
    const int wid = tid >> 5, lane = tid & 31;
    __shared__ float sred[8];

    float4 v = ((const float4*)p)[tid];
    float m = fmaxf(fmaxf(v.x, v.y), fmaxf(v.z, v.w));
    #pragma unroll
    for (int o = 16; o; o >>= 1) m = fmaxf(m, __shfl_xor_sync(0xffffffffu, m, o));
    if (lane == 0) sred[wid] = m;
    __syncthreads();
    float rm = sred[0];
    #pragma unroll
    for (int i = 1; i < 8; i++) rm = fmaxf(rm, sred[i]);
    __syncthreads();

    // e = exp(v - rm) in [0,1]; p = e / sum; max(p) = 1/sum, so quantizing e
    // with scale 1 and carrying rowscale = 1/sum is exact per-row scaling.
    v.x = __expf(v.x - rm); v.y = __expf(v.y - rm);
    v.z = __expf(v.z - rm); v.w = __expf(v.w - rm);
    float sum = (v.x + v.y) + (v.z + v.w);
    #pragma unroll
    for (int o = 16; o; o >>= 1) sum += __shfl_xor_sync(0xffffffffu, sum, o);
    if (lane == 0) sred[wid] = sum;
    __syncthreads();
    float tot = 0.f;
    #pragma unroll
    for (int i = 0; i < 8; i++) tot += sred[i];
    if (tid == 0) g_psc[row] = 1.0f / tot;

    char4 a, b;
    quant2f(v.x, 127.0f, ((int8_t*)&a)[0], ((int8_t*)&b)[0]);
    quant2f(v.y, 127.0f, ((int8_t*)&a)[1], ((int8_t*)&b)[1]);
    quant2f(v.z, 127.0f, ((int8_t*)&a)[2], ((int8_t*)&b)[2]);
    quant2f(v.w, 127.0f, ((int8_t*)&a)[3], ((int8_t*)&b)[3]);
    ((char4*)(g_p1 + row * SLK))[tid] = a;
    ((char4*)(g_p2 + row * SLK))[tid] = b;
}

// ---------------- ctx per-row absmax quantization ----------------
__global__ void __launch_bounds__(256) quant_ctx()
{
    const size_t row = blockIdx.x;
    const float* src = g_ctx + row * HD;
    const int tid = threadIdx.x;
    const int wid = tid >> 5, lane = tid & 31;
    __shared__ float sred[8];

    float4 vv[4];
    float am = 0.f;
    #pragma unroll
    for (int g = 0; g < 4; g++) {
        vv[g] = ((const float4*)src)[tid * 4 + g];
        am = fmaxf(am, fmaxf(fmaxf(fabsf(vv[g].x), fabsf(vv[g].y)),
                             fmaxf(fabsf(vv[g].z), fabsf(vv[g].w))));
    }
    #pragma unroll
    for (int o = 16; o; o >>= 1) am = fmaxf(am, __shfl_xor_sync(0xffffffffu, am, o));
    if (lane == 0) sred[wid] = am;
    __syncthreads();
    float s = sred[0];
    #pragma unroll
    for (int i = 1; i < 8; i++) s = fmaxf(s, sred[i]);
    if (s <= 0.f) s = 1.f;
    if (tid == 0) g_csc[row] = s;
    const float inv = 127.0f / s;

    #pragma unroll
    for (int g = 0; g < 4; g++) {
        char4 a, b;
        quant2f(vv[g].x, inv, ((int8_t*)&a)[0], ((int8_t*)&b)[0]);
        quant2f(vv[g].y, inv, ((int8_t*)&a)[1], ((int8_t*)&b)[1]);
        quant2f(vv[g].z, inv, ((int8_t*)&a)[2], ((int8_t*)&b)[2]);
        quant2f(vv[g].w, inv, ((int8_t*)&a)[3], ((int8_t*)&b)[3]);
        ((char4*)(g_c1 + row * HD))[tid * 4 + g] = a;
        ((char4*)(g_c2 + row * HD))[tid * 4 + g] = b;
    }
}

// ---------------- host launch ----------------
template<typename T>
static T* symaddr(const void* sym) {
    void* p = nullptr;
    cudaGetSymbolAddress(&p, sym);
    return (T*)p;
}

extern "C" void kernel_launch(void* const* d_in, const int* in_sizes, int n_in,
                              void* d_out, int out_size)
{
    const float* x      = (const float*)d_in[0];
    const float* states = (const float*)d_in[1];
    const int*   mask   = (const int*)  d_in[2];
    const float* Wq     = (const float*)d_in[3];
    const float* bq     = (const float*)d_in[4];
    const float* Wk     = (const float*)d_in[5];
    const float* bk     = (const float*)d_in[6];
    const float* Wv     = (const float*)d_in[7];
    const float* bv     = (const float*)d_in[8];
    const float* Wp     = (const float*)d_in[9];
    const float* bp     = (const float*)d_in[10];
    float* out = (float*)d_out;

    int8_t *x1 = symaddr<int8_t>(g_x1), *x2 = symaddr<int8_t>(g_x2);
    int8_t *st1 = symaddr<int8_t>(g_st1), *st2 = symaddr<int8_t>(g_st2);
    int8_t *wq1 = symaddr<int8_t>(g_wq1), *wq2 = symaddr<int8_t>(g_wq2);
    int8_t *wk1 = symaddr<int8_t>(g_wk1), *wk2 = symaddr<int8_t>(g_wk2);
    int8_t *wv1 = symaddr<int8_t>(g_wv1), *wv2 = symaddr<int8_t>(g_wv2);
    int8_t *wp1 = symaddr<int8_t>(g_wp1), *wp2 = symaddr<int8_t>(g_wp2);
    int8_t *qk1 = symaddr<int8_t>(g_qk1), *qk2 = symaddr<int8_t>(g_qk2);
    int8_t *vt1 = symaddr<int8_t>(g_vt1), *vt2 = symaddr<int8_t>(g_vt2);
    int8_t *p1 = symaddr<int8_t>(g_p1), *p2 = symaddr<int8_t>(g_p2);
    int8_t *c1 = symaddr<int8_t>(g_c1), *c2 = symaddr<int8_t>(g_c2);
    float *Sf = symaddr<float>(g_S);
    float *ctxf = symaddr<float>(g_ctx);
    float *psc = symaddr<float>(g_psc);
    float *csc = symaddr<float>(g_csc);

    cudaFuncSetAttribute(igemm<EPI_QK>,  cudaFuncAttributeMaxDynamicSharedMemorySize, GEMM_SMEM);
    cudaFuncSetAttribute(igemm<EPI_VT>,  cudaFuncAttributeMaxDynamicSharedMemorySize, GEMM_SMEM);
    cudaFuncSetAttribute(igemm<EPI_SC>,  cudaFuncAttributeMaxDynamicSharedMemorySize, GEMM_SMEM);
    cudaFuncSetAttribute(igemm<EPI_CTX>, cudaFuncAttributeMaxDynamicSharedMemorySize, GEMM_SMEM);
    cudaFuncSetAttribute(igemm<EPI_OUT>, cudaFuncAttributeMaxDynamicSharedMemorySize, GEMM_SMEM);

    // scale constants: value = (s_a*s_b/127^2) * (acc_hi + acc_mid/256)
    const double SQRT512 = 22.62741699796952;
    const float ab_proj = (float)(49.0 / (SQRT512 * 16129.0));        // s_x=7, s_w=7/sqrt512
    const float ab_sc   = (float)(49.0 / (16129.0 * SQRT512));        // s_q=s_k=7, incl 1/sqrt(512)
    const float ab_ctx  = (float)(7.0 / 16129.0);                     // s_e=1 (x rowsc), s_v=7
    const float ab_out  = (float)((7.0 / 64.0) / 16129.0);            // s_wp=7/64 (x rowsc)

    // 0: quantize all inputs
    quant_in<<<dim3(4096, 6), 256>>>(x, states, Wq, Wk, Wv, Wp,
        x1, x2, st1, st2, wq1, wq2, wk1, wk2, wv1, wv2, wp1, wp2);

    // 1: Q (z<64) / K (z>=64) projections: M=1024 N=512 K=512
    igemm<EPI_QK><<<dim3(4, 8, 128), 256, GEMM_SMEM>>>(
        x1, x2, st1, st2, DD, wq1, wq2, wk1, wk2, DD, DD,
        ab_proj, nullptr, bq, bk, nullptr, nullptr, qk1, qk2, DD);

    // 2: V projection -> V^T
    igemm<EPI_VT><<<dim3(4, 8, 64), 256, GEMM_SMEM>>>(
        st1, st2, nullptr, nullptr, DD, wv1, wv2, nullptr, nullptr, DD, DD,
        ab_proj, nullptr, bv, nullptr, nullptr, nullptr, vt1, vt2, SLK);

    // 3: scores = Q K^T / sqrt(512), masked -> fp32 S
    igemm<EPI_SC><<<dim3(8, 8, 64), 256, GEMM_SMEM>>>(
        qk1, qk2, nullptr, nullptr, DD,
        qk1 + (size_t)64 * SLQ * DD, qk2 + (size_t)64 * SLQ * DD, nullptr, nullptr, DD, DD,
        ab_sc, nullptr, nullptr, nullptr, mask, Sf, nullptr, nullptr, SLK);

    // 4: softmax + P quantization (per-row scale)
    softmax_q<<<65536, 256>>>();

    // 5 (profiled): ctx = P V -> fp32, head-concat. M=1024 N=512 K=1024
    igemm<EPI_CTX><<<dim3(4, 8, 64), 256, GEMM_SMEM>>>(
        p1, p2, nullptr, nullptr, SLK, vt1, vt2, nullptr, nullptr, SLK, SLK,
        ab_ctx, psc, nullptr, nullptr, nullptr, ctxf, nullptr, nullptr, HD);

    // 6: ctx per-row absmax quantization
    quant_ctx<<<NB * SLQ, 256>>>();

    // 7: out = ctx Wp^T + bp. M=8192 N=512 K=4096
    igemm<EPI_OUT><<<dim3(4, 64, 1), 256, GEMM_SMEM>>>(
        c1, c2, nullptr, nullptr, HD, wp1, wp2, nullptr, nullptr, HD, HD,
        ab_out, csc, bp, nullptr, nullptr, out, nullptr, nullptr, DD);
}

// round 8
// speedup vs baseline: 1.8237x; 1.8237x over previous
#include <cuda_runtime.h>
#include <cuda_bf16.h>
#include <cstdint>

// Problem dims
#define NB 8
#define NH 8
#define SLQ 1024
#define SLK 1024
#define DD 512
#define HD 4096

using bf16 = __nv_bfloat16;

// ---------------- device global scratch ----------------
__device__ bf16 g_xh[(size_t)NB*SLQ*DD],  g_xl[(size_t)NB*SLQ*DD];
__device__ bf16 g_sh[(size_t)NB*SLK*DD],  g_sl[(size_t)NB*SLK*DD];
__device__ bf16 g_Wqh[(size_t)NH*DD*DD],  g_Wql[(size_t)NH*DD*DD];
__device__ bf16 g_Wkh[(size_t)NH*DD*DD],  g_Wkl[(size_t)NH*DD*DD];
__device__ bf16 g_Wvh[(size_t)NH*DD*DD],  g_Wvl[(size_t)NH*DD*DD];
__device__ bf16 g_Wph[(size_t)DD*HD],     g_Wpl[(size_t)DD*HD];
__device__ bf16 g_QKh[(size_t)128*SLQ*DD], g_QKl[(size_t)128*SLQ*DD];  // Q: z<64, K: z>=64
__device__ bf16 g_VTh[(size_t)64*DD*SLK],  g_VTl[(size_t)64*DD*SLK];
__device__ float g_S[(size_t)64*SLQ*SLK];
__device__ bf16 g_Ph[(size_t)64*SLQ*SLK], g_Pl[(size_t)64*SLQ*SLK];
__device__ bf16 g_Ch[(size_t)NB*SLQ*HD],  g_Cl[(size_t)NB*SLQ*HD];

// ---------------- PTX helpers (baseline ISA only) ----------------
__device__ __forceinline__ uint32_t smem_u32(const void* p) {
    uint32_t a;
    asm("{ .reg .u64 t; cvta.to.shared.u64 t, %1; cvt.u32.u64 %0, t; }" : "=r"(a) : "l"(p));
    return a;
}
#define CP_ASYNC16(dst, src) \
    asm volatile("cp.async.cg.shared.global [%0], [%1], 16;" :: "r"(dst), "l"(src))
#define CP_COMMIT() asm volatile("cp.async.commit_group;" ::: "memory")
#define CP_WAIT0() asm volatile("cp.async.wait_group 0;" ::: "memory")

__device__ __forceinline__ void ldsm_x4(uint32_t* r, uint32_t addr) {
    asm volatile("ldmatrix.sync.aligned.m8n8.x4.shared.b16 {%0,%1,%2,%3}, [%4];"
        : "=r"(r[0]), "=r"(r[1]), "=r"(r[2]), "=r"(r[3]) : "r"(addr));
}
__device__ __forceinline__ void mma16816(float* d, const uint32_t* a, const uint32_t* b) {
    asm volatile("mma.sync.aligned.m16n8k16.row.col.f32.bf16.bf16.f32 "
        "{%0,%1,%2,%3}, {%4,%5,%6,%7}, {%8,%9}, {%0,%1,%2,%3};"
        : "+f"(d[0]), "+f"(d[1]), "+f"(d[2]), "+f"(d[3])
        : "r"(a[0]), "r"(a[1]), "r"(a[2]), "r"(a[3]), "r"(b[0]), "r"(b[1]));
}

// Block-linear ldmatrix-native layouts (BK=64 bf16 -> 8 x 16B columns per row).
// Each 8x16B matrix is one contiguous 128B block: conflict-free LDSM + coalesced stores.
// A plane: 256 rows; B plane: 128 rows.
__device__ __forceinline__ uint32_t blinA(int row, int c16) {
    return (uint32_t)(c16 * 4096 + ((row >> 3) << 7) + ((row & 7) << 4));
}
__device__ __forceinline__ uint32_t blinB(int row, int c16) {
    return (uint32_t)(c16 * 2048 + ((row >> 3) << 7) + ((row & 7) << 4));
}

// Tiles: CTA 256(M) x 128(N) x 64(K); warps 4x2 of 64x64.
// Stage (96KB): Ah 32K | Al 32K | Bh 16K | Bl 16K. 2 stages = 192KB.
#define OFF_AL 32768
#define OFF_BH 65536
#define OFF_BL 81920
#define STAGE_B 98304
#define GEMM_SMEM 196608

// Epilogue IDs
#define EPI_QK  0
#define EPI_VT  1
#define EPI_SC  2
#define EPI_CTX 3
#define EPI_OUT 4

template<int EPI>
__global__ void __launch_bounds__(256, 1) gemm3(
    const bf16* __restrict__ Ah, const bf16* __restrict__ Al,
    const bf16* __restrict__ A2h, const bf16* __restrict__ A2l, int lda,
    const bf16* __restrict__ Bh, const bf16* __restrict__ Bl,
    const bf16* __restrict__ B2h, const bf16* __restrict__ B2l, int ldb,
    int Ktot,
    const float* __restrict__ bias, const float* __restrict__ bias2,
    const int* __restrict__ mask,
    float* __restrict__ outf,
    bf16* __restrict__ oh, bf16* __restrict__ ol, int ldo)
{
    extern __shared__ char smem[];
    const uint32_t sb = smem_u32(smem);
    const int tid = threadIdx.x;
    const int wid = tid >> 5;
    const int lane = tid & 31;
    const int z = blockIdx.z;
    const int m0 = blockIdx.y * 256;
    const int n0 = blockIdx.x * 128;

    size_t aOff = 0, bOff = 0, oOff = 0, mOff = 0;
    if (EPI == EPI_QK) {
        const int zz = z & 63;
        if (z >= 64) { Ah = A2h; Al = A2l; Bh = B2h; Bl = B2l; bias = bias2; }
        aOff = (size_t)(zz >> 3) * SLQ * DD;
        bOff = (size_t)(zz & 7) * DD * DD;
        oOff = (size_t)z * SLQ * DD;
    } else if (EPI == EPI_VT) {
        aOff = (size_t)(z >> 3) * SLQ * DD;
        bOff = (size_t)(z & 7) * DD * DD;
        oOff = (size_t)z * DD * SLK;
    } else if (EPI == EPI_SC) {
        aOff = (size_t)z * SLQ * DD;
        bOff = (size_t)z * SLK * DD;
        oOff = (size_t)z * SLQ * SLK;
        mOff = (size_t)(z >> 3) * SLQ * SLK;
    } else if (EPI == EPI_CTX) {
        aOff = (size_t)z * SLQ * SLK;
        bOff = (size_t)z * DD * SLK;
        oOff = (size_t)(z >> 3) * SLQ * HD + (size_t)(z & 7) * DD;
    }

    // ---- loader mapping: 256 threads; c16 = tid&7, row base = tid>>3 (0..31)
    const int c16 = tid & 7;
    const int rb8 = tid >> 3;
    uint32_t dA[8], dB[4];
    #pragma unroll
    for (int i = 0; i < 8; i++) dA[i] = blinA(rb8 + 32 * i, c16);
    #pragma unroll
    for (int i = 0; i < 4; i++) dB[i] = blinB(rb8 + 32 * i, c16);
    const bf16* sAh = Ah + aOff + (size_t)(m0 + rb8) * lda + c16 * 8;
    const bf16* sAl = Al + aOff + (size_t)(m0 + rb8) * lda + c16 * 8;
    const bf16* sBh = Bh + bOff + (size_t)(n0 + rb8) * ldb + c16 * 8;
    const bf16* sBl = Bl + bOff + (size_t)(n0 + rb8) * ldb + c16 * 8;
    const size_t r32a = (size_t)32 * lda;
    const size_t r32b = (size_t)32 * ldb;

    const int NCH = Ktot >> 6;  // BK = 64

#define LOAD_CHUNK(stg, kt) do { \
    const uint32_t _b = sb + (stg) * STAGE_B; \
    _Pragma("unroll") \
    for (int i = 0; i < 8; i++) CP_ASYNC16(_b + dA[i],          sAh + (kt) + (size_t)i * r32a); \
    _Pragma("unroll") \
    for (int i = 0; i < 8; i++) CP_ASYNC16(_b + OFF_AL + dA[i], sAl + (kt) + (size_t)i * r32a); \
    _Pragma("unroll") \
    for (int i = 0; i < 4; i++) CP_ASYNC16(_b + OFF_BH + dB[i], sBh + (kt) + (size_t)i * r32b); \
    _Pragma("unroll") \
    for (int i = 0; i < 4; i++) CP_ASYNC16(_b + OFF_BL + dB[i], sBl + (kt) + (size_t)i * r32b); \
    CP_COMMIT(); } while (0)

    LOAD_CHUNK(0, 0);

    // ---- compute mapping: warp grid 4(M) x 2(N), warp tile 64x64
    const int warpM = wid >> 1;
    const int warpN = wid & 1;
    const int grp = lane >> 3;
    const int l7  = lane & 7;
    const int arowb = warpM * 64 + ((grp & 1) << 3) + l7;   // + mt*16
    const int akc   = grp >> 1;                              // + 2*ks
    const int browb = warpN * 64 + ((grp >> 1) << 3) + l7;  // + p*16
    const int bkc   = grp & 1;                               // + 2*ks

    float acc[4][8][4];
    #pragma unroll
    for (int mt = 0; mt < 4; mt++)
        #pragma unroll
        for (int nt = 0; nt < 8; nt++)
            #pragma unroll
            for (int j = 0; j < 4; j++) acc[mt][nt][j] = 0.f;

    for (int c = 0; c < NCH; c++) {
        CP_WAIT0();           // chunk c fully landed (single group outstanding)
        __syncthreads();
        // Stage (c+1)&1 was last read by compute(c-1), finished by all warps
        // before the barrier above -> safe to overwrite.
        if (c + 1 < NCH)
            LOAD_CHUNK((c + 1) & 1, (size_t)(c + 1) * 64);

        const uint32_t st = sb + (c & 1) * STAGE_B;
        #pragma unroll
        for (int ks = 0; ks < 4; ks++) {
            uint32_t ah[4][4], al[4][4];
            #pragma unroll
            for (int mt = 0; mt < 4; mt++) {
                const uint32_t off = blinA(arowb + mt * 16, 2 * ks + akc);
                ldsm_x4(ah[mt], st + off);
                ldsm_x4(al[mt], st + OFF_AL + off);
            }
            #pragma unroll
            for (int p = 0; p < 4; p++) {
                uint32_t bh[4], bl[4];
                const uint32_t off = blinB(browb + p * 16, 2 * ks + bkc);
                ldsm_x4(bh, st + OFF_BH + off);
                ldsm_x4(bl, st + OFF_BL + off);
                #pragma unroll
                for (int mt = 0; mt < 4; mt++) {
                    #pragma unroll
                    for (int h = 0; h < 2; h++) {
                        const int nt = p * 2 + h;
                        mma16816(acc[mt][nt], ah[mt], &bh[h * 2]);
                        mma16816(acc[mt][nt], ah[mt], &bl[h * 2]);
                        mma16816(acc[mt][nt], al[mt], &bh[h * 2]);
                    }
                }
            }
        }
    }

    // ---------------- epilogue ----------------
    __syncthreads();
    const int r4 = lane >> 2;
    const int c2 = (lane & 3) * 2;
    const int colb = n0 + warpN * 64 + c2;

    #pragma unroll
    for (int mt = 0; mt < 4; mt++) {
        #pragma unroll
        for (int rh = 0; rh < 2; rh++) {
            const int row = m0 + warpM * 64 + mt * 16 + rh * 8 + r4;
            if (EPI == EPI_QK || EPI == EPI_CTX) {
                const size_t rowbase = oOff + (size_t)row * ldo + colb;
                #pragma unroll
                for (int nt = 0; nt < 8; nt++) {
                    const int col = colb + nt * 8;
                    float v0 = acc[mt][nt][rh * 2 + 0];
                    float v1 = acc[mt][nt][rh * 2 + 1];
                    if (EPI == EPI_QK) { v0 += bias[col]; v1 += bias[col + 1]; }
                    bf16 h0 = __float2bfloat16(v0), h1 = __float2bfloat16(v1);
                    bf16 l0 = __float2bfloat16(v0 - __bfloat162float(h0));
                    bf16 l1 = __float2bfloat16(v1 - __bfloat162float(h1));
                    uint32_t ph = (uint32_t)*(unsigned short*)&h0 | ((uint32_t)*(unsigned short*)&h1 << 16);
                    uint32_t pl = (uint32_t)*(unsigned short*)&l0 | ((uint32_t)*(unsigned short*)&l1 << 16);
                    *(uint32_t*)(oh + rowbase + nt * 8) = ph;
                    *(uint32_t*)(ol + rowbase + nt * 8) = pl;
                }
            } else if (EPI == EPI_VT) {
                #pragma unroll
                for (int nt = 0; nt < 8; nt++) {
                    const int col = colb + nt * 8;
                    float v0 = acc[mt][nt][rh * 2 + 0] + bias[col];
                    float v1 = acc[mt][nt][rh * 2 + 1] + bias[col + 1];
                    bf16 h0 = __float2bfloat16(v0), h1 = __float2bfloat16(v1);
                    bf16 l0 = __float2bfloat16(v0 - __bfloat162float(h0));
                    bf16 l1 = __float2bfloat16(v1 - __bfloat162float(h1));
                    const size_t i0 = oOff + (size_t)col * SLK + row;
                    oh[i0] = h0; ol[i0] = l0;
                    oh[i0 + SLK] = h1; ol[i0 + SLK] = l1;
                }
            } else if (EPI == EPI_SC) {
                const float scale = 0.044194173824159216f;  // 1/sqrt(512)
                const size_t rowbase = oOff + (size_t)row * SLK + colb;
                const int* mp = mask + mOff + (size_t)row * SLK + colb;
                #pragma unroll
                for (int nt = 0; nt < 8; nt++) {
                    int2 mk = *(const int2*)(mp + nt * 8);
                    float2 o;
                    o.x = mk.x ? acc[mt][nt][rh * 2 + 0] * scale : -1e30f;
                    o.y = mk.y ? acc[mt][nt][rh * 2 + 1] * scale : -1e30f;
                    *(float2*)(outf + rowbase + nt * 8) = o;
                }
            } else {  // EPI_OUT
                const size_t rowbase = (size_t)row * ldo + colb;
                #pragma unroll
                for (int nt = 0; nt < 8; nt++) {
                    const int col = colb + nt * 8;
                    float2 o;
                    o.x = acc[mt][nt][rh * 2 + 0] + bias[col];
                    o.y = acc[mt][nt][rh * 2 + 1] + bias[col + 1];
                    *(float2*)(outf + rowbase + nt * 8) = o;
                }
            }
        }
    }
}

// ---------------- fused fp32 -> (hi, lo) bf16 conversion ----------------
__global__ void cvt_all(
    const float* __restrict__ x, const float* __restrict__ st,
    const float* __restrict__ wq, const float* __restrict__ wk,
    const float* __restrict__ wv, const float* __restrict__ wp,
    bf16* xh, bf16* xl, bf16* shh, bf16* sll,
    bf16* wqh, bf16* wql, bf16* wkh, bf16* wkl,
    bf16* wvh, bf16* wvl, bf16* wph, bf16* wpl)
{
    const int which = blockIdx.y;
    const float* s; bf16 *hi, *lo; int n4;
    if (which == 0)      { s = x;  hi = xh;  lo = xl;  n4 = NB*SLQ*DD/4; }
    else if (which == 1) { s = st; hi = shh; lo = sll; n4 = NB*SLK*DD/4; }
    else if (which == 2) { s = wq; hi = wqh; lo = wql; n4 = NH*DD*DD/4; }
    else if (which == 3) { s = wk; hi = wkh; lo = wkl; n4 = NH*DD*DD/4; }
    else if (which == 4) { s = wv; hi = wvh; lo = wvl; n4 = NH*DD*DD/4; }
    else                 { s = wp; hi = wph; lo = wpl; n4 = DD*HD/4; }
    int i = blockIdx.x * blockDim.x + threadIdx.x;
    if (i >= n4) return;
    float4 v = ((const float4*)s)[i];
    bf16 h0 = __float2bfloat16(v.x), h1 = __float2bfloat16(v.y),
         h2 = __float2bfloat16(v.z), h3 = __float2bfloat16(v.w);
    bf16 l0 = __float2bfloat16(v.x - __bfloat162float(h0));
    bf16 l1 = __float2bfloat16(v.y - __bfloat162float(h1));
    bf16 l2 = __float2bfloat16(v.z - __bfloat162float(h2));
    bf16 l3 = __float2bfloat16(v.w - __bfloat162float(h3));
    uint2 vh, vl;
    unsigned short* ph = (unsigned short*)&vh;
    unsigned short* pl = (unsigned short*)&vl;
    ph[0] = *(unsigned short*)&h0; ph[1] = *(unsigned short*)&h1;
    ph[2] = *(unsigned short*)&h2; ph[3] = *(unsigned short*)&h3;
    pl[0] = *(unsigned short*)&l0; pl[1] = *(unsigned short*)&l1;
    pl[2] = *(unsigned short*)&l2; pl[3] = *(unsigned short*)&l3;
    ((uint2*)hi)[i] = vh;
    ((uint2*)lo)[i] = vl;
}

// ---------------- softmax over Lk=1024, emit hi/lo bf16 ----------------
__global__ void __launch_bounds__(256) softmax_hl()
{
    const size_t row = blockIdx.x;
    const float* p = g_S + row * SLK;
    bf16* ph = g_Ph + row * SLK;
    bf16* pl = g_Pl + row * SLK;
    const int tid = threadIdx.x;
    const int wid = tid >> 5, lane = tid & 31;
    __shared__ float sred[8];

    float4 v = ((const float4*)p)[tid];
    float m = fmaxf(fmaxf(v.x, v.y), fmaxf(v.z, v.w));
    #pragma unroll
    for (int o = 16; o; o >>= 1) m = fmaxf(m, __shfl_xor_sync(0xffffffffu, m, o));
    if (lane == 0) sred[wid] = m;
    __syncthreads();
    float rm = sred[0];
    #pragma unroll
    for (int i = 1; i < 8; i++) rm = fmaxf(rm, sred[i]);
    __syncthreads();

    v.x = __expf(v.x - rm); v.y = __expf(v.y - rm);
    v.z = __expf(v.z - rm); v.w = __expf(v.w - rm);
    float sum = (v.x + v.y) + (v.z + v.w);
    #pragma unroll
    for (int o = 16; o; o >>= 1) sum += __shfl_xor_sync(0xffffffffu, sum, o);
    if (lane == 0) sred[wid] = sum;
    __syncthreads();
    float tot = 0.f;
    #pragma unroll
    for (int i = 0; i < 8; i++) tot += sred[i];
    const float inv = 1.0f / tot;
    v.x *= inv; v.y *= inv; v.z *= inv; v.w *= inv;

    uint2 vh, vl;
    unsigned short* qh = (unsigned short*)&vh;
    unsigned short* ql = (unsigned short*)&vl;
    float vv[4] = {v.x, v.y, v.z, v.w};
    #pragma unroll
    for (int j = 0; j < 4; j++) {
        bf16 h = __float2bfloat16(vv[j]);
        bf16 l = __float2bfloat16(vv[j] - __bfloat162float(h));
        qh[j] = *(unsigned short*)&h;
        ql[j] = *(unsigned short*)&l;
    }
    ((uint2*)ph)[tid] = vh;
    ((uint2*)pl)[tid] = vl;
}

// ---------------- host launch ----------------
template<typename T>
static T* symaddr(const void* sym) {
    void* p = nullptr;
    cudaGetSymbolAddress(&p, sym);
    return (T*)p;
}

extern "C" void kernel_launch(void* const* d_in, const int* in_sizes, int n_in,
                              void* d_out, int out_size)
{
    const float* x      = (const float*)d_in[0];
    const float* states = (const float*)d_in[1];
    const int*   mask   = (const int*)  d_in[2];
    const float* Wq     = (const float*)d_in[3];
    const float* bq     = (const float*)d_in[4];
    const float* Wk     = (const float*)d_in[5];
    const float* bk     = (const float*)d_in[6];
    const float* Wv     = (const float*)d_in[7];
    const float* bv     = (const float*)d_in[8];
    const float* Wp     = (const float*)d_in[9];
    const float* bp     = (const float*)d_in[10];
    float* out = (float*)d_out;

    bf16 *xh = symaddr<bf16>(g_xh), *xl = symaddr<bf16>(g_xl);
    bf16 *sh = symaddr<bf16>(g_sh), *sl = symaddr<bf16>(g_sl);
    bf16 *wqh = symaddr<bf16>(g_Wqh), *wql = symaddr<bf16>(g_Wql);
    bf16 *wkh = symaddr<bf16>(g_Wkh), *wkl = symaddr<bf16>(g_Wkl);
    bf16 *wvh = symaddr<bf16>(g_Wvh), *wvl = symaddr<bf16>(g_Wvl);
    bf16 *wph = symaddr<bf16>(g_Wph), *wpl = symaddr<bf16>(g_Wpl);
    bf16 *qkh = symaddr<bf16>(g_QKh), *qkl = symaddr<bf16>(g_QKl);
    bf16 *vth = symaddr<bf16>(g_VTh), *vtl = symaddr<bf16>(g_VTl);
    float *Sf = symaddr<float>(g_S);
    bf16 *phh = symaddr<bf16>(g_Ph), *pll = symaddr<bf16>(g_Pl);
    bf16 *chh = symaddr<bf16>(g_Ch), *cll = symaddr<bf16>(g_Cl);

    cudaFuncSetAttribute(gemm3<EPI_QK>,  cudaFuncAttributeMaxDynamicSharedMemorySize, GEMM_SMEM);
    cudaFuncSetAttribute(gemm3<EPI_VT>,  cudaFuncAttributeMaxDynamicSharedMemorySize, GEMM_SMEM);
    cudaFuncSetAttribute(gemm3<EPI_SC>,  cudaFuncAttributeMaxDynamicSharedMemorySize, GEMM_SMEM);
    cudaFuncSetAttribute(gemm3<EPI_CTX>, cudaFuncAttributeMaxDynamicSharedMemorySize, GEMM_SMEM);
    cudaFuncSetAttribute(gemm3<EPI_OUT>, cudaFuncAttributeMaxDynamicSharedMemorySize, GEMM_SMEM);

    // Launch 0: all conversions in one grid
    cvt_all<<<dim3(4096, 6), 256>>>(x, states, Wq, Wk, Wv, Wp,
        xh, xl, sh, sl, wqh, wql, wkh, wkl, wvh, wvl, wph, wpl);

    // Launch 1: Q (z<64) and K (z>=64) projections, M=1024 N=512 K=512
    gemm3<EPI_QK><<<dim3(4, 4, 128), 256, GEMM_SMEM>>>(
        xh, xl, sh, sl, DD, wqh, wql, wkh, wkl, DD, DD,
        bq, bk, nullptr, nullptr, qkh, qkl, DD);

    // Launch 2: V projection -> V^T
    gemm3<EPI_VT><<<dim3(4, 4, 64), 256, GEMM_SMEM>>>(
        sh, sl, nullptr, nullptr, DD, wvh, wvl, nullptr, nullptr, DD, DD,
        bv, nullptr, nullptr, nullptr, vth, vtl, SLK);

    // Launch 3: scores = Q K^T * scale, masked (M=1024, N=1024, K=512)
    gemm3<EPI_SC><<<dim3(8, 4, 64), 256, GEMM_SMEM>>>(
        qkh, qkl, nullptr, nullptr, DD,
        qkh + (size_t)64 * SLQ * DD, qkl + (size_t)64 * SLQ * DD, nullptr, nullptr, DD, DD,
        nullptr, nullptr, mask, Sf, nullptr, nullptr, SLK);

    // Launch 4: softmax + split
    softmax_hl<<<65536, 256>>>();

    // Launch 5 (profiled): ctx = P V^T-form (M=1024, N=512, K=1024)
    gemm3<EPI_CTX><<<dim3(4, 4, 64), 256, GEMM_SMEM>>>(
        phh, pll, nullptr, nullptr, SLK, vth, vtl, nullptr, nullptr, SLK, SLK,
        nullptr, nullptr, nullptr, nullptr, chh, cll, HD);

    // Launch 6: out = C Wp^T + bp (M=8192, N=512, K=4096)
    gemm3<EPI_OUT><<<dim3(4, 32, 1), 256, GEMM_SMEM>>>(
        chh, cll, nullptr, nullptr, HD, wph, wpl, nullptr, nullptr, HD, HD,
        bp, nullptr, nullptr, out, nullptr, nullptr, DD);
}

// round 9
// speedup vs baseline: 3.3485x; 1.8361x over previous
#include <cuda_runtime.h>
#include <cuda_fp16.h>
#include <cstdint>

// Problem dims
#define NB 8
#define NH 8
#define SLQ 1024
#define SLK 1024
#define DD 512
#define HD 4096

using hf = __half;

// ---------------- device global scratch ----------------
__device__ hf g_xh[(size_t)NB*SLQ*DD],  g_xl[(size_t)NB*SLQ*DD];
__device__ hf g_sh[(size_t)NB*SLK*DD],  g_sl[(size_t)NB*SLK*DD];
__device__ hf g_Wqh[(size_t)NH*DD*DD],  g_Wql[(size_t)NH*DD*DD];
__device__ hf g_Wkh[(size_t)NH*DD*DD],  g_Wkl[(size_t)NH*DD*DD];
__device__ hf g_Wvh[(size_t)NH*DD*DD],  g_Wvl[(size_t)NH*DD*DD];
__device__ hf g_Wph[(size_t)DD*HD],     g_Wpl[(size_t)DD*HD];
__device__ hf g_QKh[(size_t)128*SLQ*DD], g_QKl[(size_t)128*SLQ*DD];  // Q: z<64, K: z>=64
__device__ hf g_VTh[(size_t)64*DD*SLK],  g_VTl[(size_t)64*DD*SLK];
__device__ float g_S[(size_t)64*SLQ*SLK];
__device__ hf g_Ph[(size_t)64*SLQ*SLK], g_Pl[(size_t)64*SLQ*SLK];
__device__ hf g_Ch[(size_t)NB*SLQ*HD],  g_Cl[(size_t)NB*SLQ*HD];

// ---------------- PTX helpers (baseline ISA only) ----------------
__device__ __forceinline__ uint32_t smem_u32(const void* p) {
    uint32_t a;
    asm("{ .reg .u64 t; cvta.to.shared.u64 t, %1; cvt.u32.u64 %0, t; }" : "=r"(a) : "l"(p));
    return a;
}
#define CP_ASYNC16(dst, src) \
    asm volatile("cp.async.cg.shared.global [%0], [%1], 16;" :: "r"(dst), "l"(src))
#define CP_COMMIT() asm volatile("cp.async.commit_group;" ::: "memory")
#define CP_WAIT1() asm volatile("cp.async.wait_group 1;" ::: "memory")
#define CP_WAIT0() asm volatile("cp.async.wait_group 0;" ::: "memory")

__device__ __forceinline__ void ldsm_x4(uint32_t* r, uint32_t addr) {
    asm volatile("ldmatrix.sync.aligned.m8n8.x4.shared.b16 {%0,%1,%2,%3}, [%4];"
        : "=r"(r[0]), "=r"(r[1]), "=r"(r[2]), "=r"(r[3]) : "r"(addr));
}
__device__ __forceinline__ void mma16816(float* d, const uint32_t* a, const uint32_t* b) {
    asm volatile("mma.sync.aligned.m16n8k16.row.col.f32.f16.f16.f32 "
        "{%0,%1,%2,%3}, {%4,%5,%6,%7}, {%8,%9}, {%0,%1,%2,%3};"
        : "+f"(d[0]), "+f"(d[1]), "+f"(d[2]), "+f"(d[3])
        : "r"(a[0]), "r"(a[1]), "r"(a[2]), "r"(a[3]), "r"(b[0]), "r"(b[1]));
}

// 64B-row swizzle: slot' = chunk ^ ((row>>1)&3), conflict-free for ldmatrix groups
__device__ __forceinline__ uint32_t swzoff(int row, int chunk) {
    return (uint32_t)row * 64u + (uint32_t)((chunk ^ ((row >> 1) & 3)) << 4);
}

// fp16 two-digit split
__device__ __forceinline__ void split2h(float v, unsigned short& h, unsigned short& l) {
    hf h0 = __float2half_rn(v);
    hf l0 = __float2half_rn(v - __half2float(h0));
    h = *(unsigned short*)&h0;
    l = *(unsigned short*)&l0;
}

// Tiles: CTA 256(M) x 128(N) x 32(K); warps 4x2 of 64x64 (R4-proven schedule)
// SMEM stage: Ah 16K | Al 16K | Bh 8K | Bl 8K = 48KB; 2 stages = 96KB
#define OFF_AL 16384
#define OFF_BH 32768
#define OFF_BL 40960
#define STAGE_B 49152
#define GEMM_SMEM 98304

// Epilogue IDs
#define EPI_QK  0  // dual-source, bias + split hi/lo, row-major
#define EPI_VT  1  // bias + split hi/lo, transposed (write V^T)
#define EPI_SC  2  // scale + mask -> fp32
#define EPI_CTX 3  // split hi/lo, row-major (head-concat via oOff)
#define EPI_OUT 4  // bias -> fp32

// NPROD: 3 = full split-split (Ahi*Bhi + Ahi*Blo + Alo*Bhi)
//        2 = split-A x single-B (Ahi*Bh + Alo*Bh); Bl plane not loaded
template<int EPI, int NPROD>
__global__ void __launch_bounds__(256, 1) gemm3(
    const hf* __restrict__ Ah, const hf* __restrict__ Al,
    const hf* __restrict__ A2h, const hf* __restrict__ A2l, int lda,
    const hf* __restrict__ Bh, const hf* __restrict__ Bl,
    const hf* __restrict__ B2h, const hf* __restrict__ B2l, int ldb,
    int Ktot,
    const float* __restrict__ bias, const float* __restrict__ bias2,
    const int* __restrict__ mask,
    float* __restrict__ outf,
    hf* __restrict__ oh, hf* __restrict__ ol, int ldo)
{
    extern __shared__ char smem[];
    const uint32_t sb = smem_u32(smem);
    const int tid = threadIdx.x;
    const int wid = tid >> 5;
    const int lane = tid & 31;
    const int z = blockIdx.z;
    const int m0 = blockIdx.y * 256;
    const int n0 = blockIdx.x * 128;

    size_t aOff = 0, bOff = 0, oOff = 0, mOff = 0;
    if (EPI == EPI_QK) {
        const int zz = z & 63;
        if (z >= 64) { Ah = A2h; Al = A2l; Bh = B2h; Bl = B2l; bias = bias2; }
        aOff = (size_t)(zz >> 3) * SLQ * DD;
        bOff = (size_t)(zz & 7) * DD * DD;
        oOff = (size_t)z * SLQ * DD;
    } else if (EPI == EPI_VT) {
        aOff = (size_t)(z >> 3) * SLQ * DD;
        bOff = (size_t)(z & 7) * DD * DD;
        oOff = (size_t)z * DD * SLK;
    } else if (EPI == EPI_SC) {
        aOff = (size_t)z * SLQ * DD;
        bOff = (size_t)z * SLK * DD;
        oOff = (size_t)z * SLQ * SLK;
        mOff = (size_t)(z >> 3) * SLQ * SLK;
    } else if (EPI == EPI_CTX) {
        aOff = (size_t)z * SLQ * SLK;
        bOff = (size_t)z * DD * SLK;
        oOff = (size_t)(z >> 3) * SLQ * HD + (size_t)(z & 7) * DD;
    }

    // ---- loader mapping: 256 threads; A: 4 row-passes, B: 2
    const int lc = tid & 3;     // 16B k-chunk (0..3)
    const int lr = tid >> 2;    // row 0..63
    uint32_t soff[4];
    #pragma unroll
    for (int i = 0; i < 4; i++)
        soff[i] = swzoff(lr + 64 * i, lc);
    const hf* sAh = Ah + aOff + (size_t)(m0 + lr) * lda + lc * 8;
    const hf* sAl = Al + aOff + (size_t)(m0 + lr) * lda + lc * 8;
    const hf* sBh = Bh + bOff + (size_t)(n0 + lr) * ldb + lc * 8;
    const hf* sBl = (NPROD == 3) ? (Bl + bOff + (size_t)(n0 + lr) * ldb + lc * 8) : nullptr;

    const int NCH = Ktot >> 5;  // BK = 32

#define LOAD_CHUNK(stg, kt) do { \
    const uint32_t _b = sb + (stg) * STAGE_B; \
    _Pragma("unroll") \
    for (int i = 0; i < 4; i++) CP_ASYNC16(_b + soff[i],          sAh + (kt) + (size_t)(64 * i) * lda); \
    _Pragma("unroll") \
    for (int i = 0; i < 4; i++) CP_ASYNC16(_b + OFF_AL + soff[i], sAl + (kt) + (size_t)(64 * i) * lda); \
    _Pragma("unroll") \
    for (int i = 0; i < 2; i++) CP_ASYNC16(_b + OFF_BH + soff[i], sBh + (kt) + (size_t)(64 * i) * ldb); \
    if (NPROD == 3) { \
        _Pragma("unroll") \
        for (int i = 0; i < 2; i++) CP_ASYNC16(_b + OFF_BL + soff[i], sBl + (kt) + (size_t)(64 * i) * ldb); \
    } \
    CP_COMMIT(); } while (0)

    LOAD_CHUNK(0, 0);

    // ---- compute mapping: warp grid 4(M) x 2(N), warp tile 64x64
    const int warpM = wid >> 1;
    const int warpN = wid & 1;
    const int grp = lane >> 3;
    const int l7  = lane & 7;
    const int arowb = warpM * 64 + ((grp & 1) << 3) + l7;   // + mt*16
    const int achb  = grp >> 1;                              // + ks*2
    const int browb = warpN * 64 + ((grp >> 1) << 3) + l7;  // + p*16
    const int bchb  = grp & 1;                               // + ks*2

    float acc[4][8][4];
    #pragma unroll
    for (int mt = 0; mt < 4; mt++)
        #pragma unroll
        for (int nt = 0; nt < 8; nt++)
            #pragma unroll
            for (int j = 0; j < 4; j++) acc[mt][nt][j] = 0.f;

    for (int c = 0; c < NCH; c++) {
        if (c + 1 < NCH) {
            LOAD_CHUNK((c + 1) & 1, (size_t)(c + 1) * 32);
            CP_WAIT1();
        } else {
            CP_WAIT0();
        }
        __syncthreads();

        const uint32_t st = sb + (c & 1) * STAGE_B;
        #pragma unroll
        for (int ks = 0; ks < 2; ks++) {
            uint32_t ah[4][4], al[4][4];
            #pragma unroll
            for (int mt = 0; mt < 4; mt++) {
                const uint32_t off = swzoff(arowb + mt * 16, achb + ks * 2);
                ldsm_x4(ah[mt], st + off);
                ldsm_x4(al[mt], st + OFF_AL + off);
            }
            #pragma unroll
            for (int p = 0; p < 4; p++) {
                uint32_t bh[4], bl[4];
                const uint32_t off = swzoff(browb + p * 16, bchb + ks * 2);
                ldsm_x4(bh, st + OFF_BH + off);
                if (NPROD == 3) ldsm_x4(bl, st + OFF_BL + off);
                #pragma unroll
                for (int mt = 0; mt < 4; mt++) {
                    #pragma unroll
                    for (int h = 0; h < 2; h++) {
                        const int nt = p * 2 + h;
                        mma16816(acc[mt][nt], ah[mt], &bh[h * 2]);
                        if (NPROD == 3) mma16816(acc[mt][nt], ah[mt], &bl[h * 2]);
                        mma16816(acc[mt][nt], al[mt], &bh[h * 2]);
                    }
                }
            }
        }
        __syncthreads();
    }

    // ---------------- epilogue ----------------
    const int r4 = lane >> 2;
    const int c2 = (lane & 3) * 2;
    const int colb = n0 + warpN * 64 + c2;

    #pragma unroll
    for (int mt = 0; mt < 4; mt++) {
        #pragma unroll
        for (int rh = 0; rh < 2; rh++) {
            const int row = m0 + warpM * 64 + mt * 16 + rh * 8 + r4;
            if (EPI == EPI_QK || EPI == EPI_CTX) {
                const size_t rowbase = oOff + (size_t)row * ldo + colb;
                #pragma unroll
                for (int nt = 0; nt < 8; nt++) {
                    const int col = colb + nt * 8;
                    float v0 = acc[mt][nt][rh * 2 + 0];
                    float v1 = acc[mt][nt][rh * 2 + 1];
                    if (EPI == EPI_QK) { v0 += bias[col]; v1 += bias[col + 1]; }
                    unsigned short h0, l0, h1, l1;
                    split2h(v0, h0, l0);
                    split2h(v1, h1, l1);
                    uint32_t ph = (uint32_t)h0 | ((uint32_t)h1 << 16);
                    uint32_t pl = (uint32_t)l0 | ((uint32_t)l1 << 16);
                    *(uint32_t*)(oh + rowbase + nt * 8) = ph;
                    *(uint32_t*)(ol + rowbase + nt * 8) = pl;
                }
            } else if (EPI == EPI_VT) {
                #pragma unroll
                for (int nt = 0; nt < 8; nt++) {
                    const int col = colb + nt * 8;
                    float v0 = acc[mt][nt][rh * 2 + 0] + bias[col];
                    float v1 = acc[mt][nt][rh * 2 + 1] + bias[col + 1];
                    unsigned short h0, l0, h1, l1;
                    split2h(v0, h0, l0);
                    split2h(v1, h1, l1);
                    const size_t i0 = oOff + (size_t)col * SLK + row;
                    *(unsigned short*)(oh + i0) = h0;
                    *(unsigned short*)(ol + i0) = l0;
                    *(unsigned short*)(oh + i0 + SLK) = h1;
                    *(unsigned short*)(ol + i0 + SLK) = l1;
                }
            } else if (EPI == EPI_SC) {
                const float scale = 0.044194173824159216f;  // 1/sqrt(512)
                const size_t rowbase = oOff + (size_t)row * SLK + colb;
                const int* mp = mask + mOff + (size_t)row * SLK + colb;
                #pragma unroll
                for (int nt = 0; nt < 8; nt++) {
                    int2 mk = *(const int2*)(mp + nt * 8);
                    float2 o;
                    o.x = mk.x ? acc[mt][nt][rh * 2 + 0] * scale : -1e30f;
                    o.y = mk.y ? acc[mt][nt][rh * 2 + 1] * scale : -1e30f;
                    *(float2*)(outf + rowbase + nt * 8) = o;
                }
            } else {  // EPI_OUT
                const size_t rowbase = (size_t)row * ldo + colb;
                #pragma unroll
                for (int nt = 0; nt < 8; nt++) {
                    const int col = colb + nt * 8;
                    float2 o;
                    o.x = acc[mt][nt][rh * 2 + 0] + bias[col];
                    o.y = acc[mt][nt][rh * 2 + 1] + bias[col + 1];
                    *(float2*)(outf + rowbase + nt * 8) = o;
                }
            }
        }
    }
}

// ---------------- fused fp32 -> (hi, lo) fp16 conversion ----------------
__global__ void cvt_all(
    const float* __restrict__ x, const float* __restrict__ st,
    const float* __restrict__ wq, const float* __restrict__ wk,
    const float* __restrict__ wv, const float* __restrict__ wp,
    hf* xh, hf* xl, hf* shh, hf* sll,
    hf* wqh, hf* wql, hf* wkh, hf* wkl,
    hf* wvh, hf* wvl, hf* wph, hf* wpl)
{
    const int which = blockIdx.y;
    const float* s; hf *hi, *lo; int n4;
    if (which == 0)      { s = x;  hi = xh;  lo = xl;  n4 = NB*SLQ*DD/4; }
    else if (which == 1) { s = st; hi = shh; lo = sll; n4 = NB*SLK*DD/4; }
    else if (which == 2) { s = wq; hi = wqh; lo = wql; n4 = NH*DD*DD/4; }
    else if (which == 3) { s = wk; hi = wkh; lo = wkl; n4 = NH*DD*DD/4; }
    else if (which == 4) { s = wv; hi = wvh; lo = wvl; n4 = NH*DD*DD/4; }
    else                 { s = wp; hi = wph; lo = wpl; n4 = DD*HD/4; }
    int i = blockIdx.x * blockDim.x + threadIdx.x;
    if (i >= n4) return;
    float4 v = ((const float4*)s)[i];
    uint2 vh, vl;
    unsigned short* ph = (unsigned short*)&vh;
    unsigned short* pl = (unsigned short*)&vl;
    split2h(v.x, ph[0], pl[0]);
    split2h(v.y, ph[1], pl[1]);
    split2h(v.z, ph[2], pl[2]);
    split2h(v.w, ph[3], pl[3]);
    ((uint2*)hi)[i] = vh;
    ((uint2*)lo)[i] = vl;
}

// ---------------- softmax over Lk=1024, emit hi/lo fp16 ----------------
__global__ void __launch_bounds__(256) softmax_hl()
{
    const size_t row = blockIdx.x;
    const float* p = g_S + row * SLK;
    hf* ph = g_Ph + row * SLK;
    hf* pl = g_Pl + row * SLK;
    const int tid = threadIdx.x;
    const int wid = tid >> 5, lane = tid & 31;
    __shared__ float sred[8];

    float4 v = ((const float4*)p)[tid];
    float m = fmaxf(fmaxf(v.x, v.y), fmaxf(v.z, v.w));
    #pragma unroll
    for (int o = 16; o; o >>= 1) m = fmaxf(m, __shfl_xor_sync(0xffffffffu, m, o));
    if (lane == 0) sred[wid] = m;
    __syncthreads();
    float rm = sred[0];
    #pragma unroll
    for (int i = 1; i < 8; i++) rm = fmaxf(rm, sred[i]);
    __syncthreads();

    v.x = __expf(v.x - rm); v.y = __expf(v.y - rm);
    v.z = __expf(v.z - rm); v.w = __expf(v.w - rm);
    float sum = (v.x + v.y) + (v.z + v.w);
    #pragma unroll
    for (int o = 16; o; o >>= 1) sum += __shfl_xor_sync(0xffffffffu, sum, o);
    if (lane == 0) sred[wid] = sum;
    __syncthreads();
    float tot = 0.f;
    #pragma unroll
    for (int i = 0; i < 8; i++) tot += sred[i];
    const float inv = 1.0f / tot;
    v.x *= inv; v.y *= inv; v.z *= inv; v.w *= inv;

    uint2 vh, vl;
    unsigned short* qh = (unsigned short*)&vh;
    unsigned short* ql = (unsigned short*)&vl;
    split2h(v.x, qh[0], ql[0]);
    split2h(v.y, qh[1], ql[1]);
    split2h(v.z, qh[2], ql[2]);
    split2h(v.w, qh[3], ql[3]);
    ((uint2*)ph)[tid] = vh;
    ((uint2*)pl)[tid] = vl;
}

// ---------------- host launch ----------------
template<typename T>
static T* symaddr(const void* sym) {
    void* p = nullptr;
    cudaGetSymbolAddress(&p, sym);
    return (T*)p;
}

extern "C" void kernel_launch(void* const* d_in, const int* in_sizes, int n_in,
                              void* d_out, int out_size)
{
    const float* x      = (const float*)d_in[0];
    const float* states = (const float*)d_in[1];
    const int*   mask   = (const int*)  d_in[2];
    const float* Wq     = (const float*)d_in[3];
    const float* bq     = (const float*)d_in[4];
    const float* Wk     = (const float*)d_in[5];
    const float* bk     = (const float*)d_in[6];
    const float* Wv     = (const float*)d_in[7];
    const float* bv     = (const float*)d_in[8];
    const float* Wp     = (const float*)d_in[9];
    const float* bp     = (const float*)d_in[10];
    float* out = (float*)d_out;

    hf *xh = symaddr<hf>(g_xh), *xl = symaddr<hf>(g_xl);
    hf *sh = symaddr<hf>(g_sh), *sl = symaddr<hf>(g_sl);
    hf *wqh = symaddr<hf>(g_Wqh), *wql = symaddr<hf>(g_Wql);
    hf *wkh = symaddr<hf>(g_Wkh), *wkl = symaddr<hf>(g_Wkl);
    hf *wvh = symaddr<hf>(g_Wvh), *wvl = symaddr<hf>(g_Wvl);
    hf *wph = symaddr<hf>(g_Wph), *wpl = symaddr<hf>(g_Wpl);
    hf *qkh = symaddr<hf>(g_QKh), *qkl = symaddr<hf>(g_QKl);
    hf *vth = symaddr<hf>(g_VTh), *vtl = symaddr<hf>(g_VTl);
    float *Sf = symaddr<float>(g_S);
    hf *phh = symaddr<hf>(g_Ph), *pll = symaddr<hf>(g_Pl);
    hf *chh = symaddr<hf>(g_Ch), *cll = symaddr<hf>(g_Cl);

    cudaFuncSetAttribute((const void*)gemm3<EPI_QK, 3>,  cudaFuncAttributeMaxDynamicSharedMemorySize, GEMM_SMEM);
    cudaFuncSetAttribute((const void*)gemm3<EPI_VT, 3>,  cudaFuncAttributeMaxDynamicSharedMemorySize, GEMM_SMEM);
    cudaFuncSetAttribute((const void*)gemm3<EPI_SC, 2>,  cudaFuncAttributeMaxDynamicSharedMemorySize, GEMM_SMEM);
    cudaFuncSetAttribute((const void*)gemm3<EPI_CTX, 2>, cudaFuncAttributeMaxDynamicSharedMemorySize, GEMM_SMEM);
    cudaFuncSetAttribute((const void*)gemm3<EPI_OUT, 3>, cudaFuncAttributeMaxDynamicSharedMemorySize, GEMM_SMEM);

    // Launch 0: all conversions in one grid
    cvt_all<<<dim3(4096, 6), 256>>>(x, states, Wq, Wk, Wv, Wp,
        xh, xl, sh, sl, wqh, wql, wkh, wkl, wvh, wvl, wph, wpl);

    // Launch 1: Q (z<64) and K (z>=64) projections, M=1024 N=512 K=512 (3-product)
    gemm3<EPI_QK, 3><<<dim3(4, 4, 128), 256, GEMM_SMEM>>>(
        xh, xl, sh, sl, DD, wqh, wql, wkh, wkl, DD, DD,
        bq, bk, nullptr, nullptr, qkh, qkl, DD);

    // Launch 2: V projection -> V^T (3-product)
    gemm3<EPI_VT, 3><<<dim3(4, 4, 64), 256, GEMM_SMEM>>>(
        sh, sl, nullptr, nullptr, DD, wvh, wvl, nullptr, nullptr, DD, DD,
        bv, nullptr, nullptr, nullptr, vth, vtl, SLK);

    // Launch 3: scores = Q K^T * scale, masked (2-product: Q split, K single)
    gemm3<EPI_SC, 2><<<dim3(8, 4, 64), 256, GEMM_SMEM>>>(
        qkh, qkl, nullptr, nullptr, DD,
        qkh + (size_t)64 * SLQ * DD, nullptr, nullptr, nullptr, DD, DD,
        nullptr, nullptr, mask, Sf, nullptr, nullptr, SLK);

    // Launch 4: softmax + split
    softmax_hl<<<65536, 256>>>();

    // Launch 5 (profiled): ctx = P V (2-product: P split, V^T single)
    gemm3<EPI_CTX, 2><<<dim3(4, 4, 64), 256, GEMM_SMEM>>>(
        phh, pll, nullptr, nullptr, SLK, vth, nullptr, nullptr, nullptr, SLK, SLK,
        nullptr, nullptr, nullptr, nullptr, chh, cll, HD);

    // Launch 6: out = C Wp^T + bp (3-product)
    gemm3<EPI_OUT, 3><<<dim3(4, 32, 1), 256, GEMM_SMEM>>>(
        chh, cll, nullptr, nullptr, HD, wph, wpl, nullptr, nullptr, HD, HD,
        bp, nullptr, nullptr, out, nullptr, nullptr, DD);
}

// round 10
// speedup vs baseline: 3.9478x; 1.1790x over previous
#include <cuda_runtime.h>
#include <cuda_fp16.h>
#include <cstdint>

// Problem dims
#define NB 8
#define NH 8
#define SLQ 1024
#define SLK 1024
#define DD 512
#define HD 4096

using hf = __half;

// ---------------- device global scratch ----------------
__device__ hf g_xh[(size_t)NB*SLQ*DD],  g_xl[(size_t)NB*SLQ*DD];
__device__ hf g_sh[(size_t)NB*SLK*DD],  g_sl[(size_t)NB*SLK*DD];
__device__ hf g_Wq[(size_t)NH*DD*DD];
__device__ hf g_Wk[(size_t)NH*DD*DD];
__device__ hf g_Wv[(size_t)NH*DD*DD];
__device__ hf g_Wp[(size_t)DD*HD];
__device__ hf g_QKh[(size_t)128*SLQ*DD], g_QKl[(size_t)128*SLQ*DD];  // Q: z<64, K: z>=64
__device__ hf g_VT[(size_t)64*DD*SLK];
__device__ float g_S[(size_t)64*SLQ*SLK];
__device__ hf g_Ph[(size_t)64*SLQ*SLK], g_Pl[(size_t)64*SLQ*SLK];
__device__ hf g_Ch[(size_t)NB*SLQ*HD],  g_Cl[(size_t)NB*SLQ*HD];

// ---------------- PTX helpers (baseline ISA only) ----------------
__device__ __forceinline__ uint32_t smem_u32(const void* p) {
    uint32_t a;
    asm("{ .reg .u64 t; cvta.to.shared.u64 t, %1; cvt.u32.u64 %0, t; }" : "=r"(a) : "l"(p));
    return a;
}
#define CP_ASYNC16(dst, src) \
    asm volatile("cp.async.cg.shared.global [%0], [%1], 16;" :: "r"(dst), "l"(src))
#define CP_COMMIT() asm volatile("cp.async.commit_group;" ::: "memory")
#define CP_WAIT1() asm volatile("cp.async.wait_group 1;" ::: "memory")
#define CP_WAIT0() asm volatile("cp.async.wait_group 0;" ::: "memory")

__device__ __forceinline__ void ldsm_x4(uint32_t* r, uint32_t addr) {
    asm volatile("ldmatrix.sync.aligned.m8n8.x4.shared.b16 {%0,%1,%2,%3}, [%4];"
        : "=r"(r[0]), "=r"(r[1]), "=r"(r[2]), "=r"(r[3]) : "r"(addr));
}
__device__ __forceinline__ void mma16816(float* d, const uint32_t* a, const uint32_t* b) {
    asm volatile("mma.sync.aligned.m16n8k16.row.col.f32.f16.f16.f32 "
        "{%0,%1,%2,%3}, {%4,%5,%6,%7}, {%8,%9}, {%0,%1,%2,%3};"
        : "+f"(d[0]), "+f"(d[1]), "+f"(d[2]), "+f"(d[3])
        : "r"(a[0]), "r"(a[1]), "r"(a[2]), "r"(a[3]), "r"(b[0]), "r"(b[1]));
}

// 64B-row swizzle: slot' = chunk ^ ((row>>1)&3), conflict-free for ldmatrix groups
__device__ __forceinline__ uint32_t swzoff(int row, int chunk) {
    return (uint32_t)row * 64u + (uint32_t)((chunk ^ ((row >> 1) & 3)) << 4);
}

// fp16 two-digit split
__device__ __forceinline__ void split2h(float v, unsigned short& h, unsigned short& l) {
    hf h0 = __float2half_rn(v);
    hf l0 = __float2half_rn(v - __half2float(h0));
    h = *(unsigned short*)&h0;
    l = *(unsigned short*)&l0;
}

// Tiles: CTA 256(M) x 128(N) x 32(K); warps 4x2 of 64x64 (R4/R9-proven schedule)
// SMEM stage: Ah 16K | Al 16K | Bh 8K | (Bl 8K unused in 2-prod) = 48KB; 2 stages = 96KB
#define OFF_AL 16384
#define OFF_BH 32768
#define STAGE_B 49152
#define GEMM_SMEM 98304

// Epilogue IDs
#define EPI_QK  0  // dual-source, bias + split hi/lo, row-major
#define EPI_VT  1  // bias + single fp16, transposed (write V^T)
#define EPI_SC  2  // scale + mask -> fp32
#define EPI_CTX 3  // split hi/lo, row-major (head-concat via oOff)
#define EPI_OUT 4  // bias -> fp32

// All GEMMs 2-product: D = Ahi*B + Alo*B  (A split fp16, B single fp16)
template<int EPI>
__global__ void __launch_bounds__(256, 1) gemm2(
    const hf* __restrict__ Ah, const hf* __restrict__ Al,
    const hf* __restrict__ A2h, const hf* __restrict__ A2l, int lda,
    const hf* __restrict__ Bh, const hf* __restrict__ B2h, int ldb,
    int Ktot,
    const float* __restrict__ bias, const float* __restrict__ bias2,
    const int* __restrict__ mask,
    float* __restrict__ outf,
    hf* __restrict__ oh, hf* __restrict__ ol, int ldo)
{
    extern __shared__ char smem[];
    const uint32_t sb = smem_u32(smem);
    const int tid = threadIdx.x;
    const int wid = tid >> 5;
    const int lane = tid & 31;
    const int z = blockIdx.z;
    const int m0 = blockIdx.y * 256;
    const int n0 = blockIdx.x * 128;

    size_t aOff = 0, bOff = 0, oOff = 0, mOff = 0;
    if (EPI == EPI_QK) {
        const int zz = z & 63;
        if (z >= 64) { Ah = A2h; Al = A2l; Bh = B2h; bias = bias2; }
        aOff = (size_t)(zz >> 3) * SLQ * DD;
        bOff = (size_t)(zz & 7) * DD * DD;
        oOff = (size_t)z * SLQ * DD;
    } else if (EPI == EPI_VT) {
        aOff = (size_t)(z >> 3) * SLQ * DD;
        bOff = (size_t)(z & 7) * DD * DD;
        oOff = (size_t)z * DD * SLK;
    } else if (EPI == EPI_SC) {
        aOff = (size_t)z * SLQ * DD;
        bOff = (size_t)z * SLK * DD;
        oOff = (size_t)z * SLQ * SLK;
        mOff = (size_t)(z >> 3) * SLQ * SLK;
    } else if (EPI == EPI_CTX) {
        aOff = (size_t)z * SLQ * SLK;
        bOff = (size_t)z * DD * SLK;
        oOff = (size_t)(z >> 3) * SLQ * HD + (size_t)(z & 7) * DD;
    }

    // ---- loader mapping: 256 threads; A: 4 row-passes, B: 2
    const int lc = tid & 3;     // 16B k-chunk (0..3)
    const int lr = tid >> 2;    // row 0..63
    uint32_t soff[4];
    #pragma unroll
    for (int i = 0; i < 4; i++)
        soff[i] = swzoff(lr + 64 * i, lc);
    const hf* sAh = Ah + aOff + (size_t)(m0 + lr) * lda + lc * 8;
    const hf* sAl = Al + aOff + (size_t)(m0 + lr) * lda + lc * 8;
    const hf* sBh = Bh + bOff + (size_t)(n0 + lr) * ldb + lc * 8;

    const int NCH = Ktot >> 5;  // BK = 32

#define LOAD_CHUNK(stg, kt) do { \
    const uint32_t _b = sb + (stg) * STAGE_B; \
    _Pragma("unroll") \
    for (int i = 0; i < 4; i++) CP_ASYNC16(_b + soff[i],          sAh + (kt) + (size_t)(64 * i) * lda); \
    _Pragma("unroll") \
    for (int i = 0; i < 4; i++) CP_ASYNC16(_b + OFF_AL + soff[i], sAl + (kt) + (size_t)(64 * i) * lda); \
    _Pragma("unroll") \
    for (int i = 0; i < 2; i++) CP_ASYNC16(_b + OFF_BH + soff[i], sBh + (kt) + (size_t)(64 * i) * ldb); \
    CP_COMMIT(); } while (0)

    LOAD_CHUNK(0, 0);

    // ---- compute mapping: warp grid 4(M) x 2(N), warp tile 64x64
    const int warpM = wid >> 1;
    const int warpN = wid & 1;
    const int grp = lane >> 3;
    const int l7  = lane & 7;
    const int arowb = warpM * 64 + ((grp & 1) << 3) + l7;   // + mt*16
    const int achb  = grp >> 1;                              // + ks*2
    const int browb = warpN * 64 + ((grp >> 1) << 3) + l7;  // + p*16
    const int bchb  = grp & 1;                               // + ks*2

    float acc[4][8][4];
    #pragma unroll
    for (int mt = 0; mt < 4; mt++)
        #pragma unroll
        for (int nt = 0; nt < 8; nt++)
            #pragma unroll
            for (int j = 0; j < 4; j++) acc[mt][nt][j] = 0.f;

    for (int c = 0; c < NCH; c++) {
        if (c + 1 < NCH) {
            LOAD_CHUNK((c + 1) & 1, (size_t)(c + 1) * 32);
            CP_WAIT1();
        } else {
            CP_WAIT0();
        }
        __syncthreads();

        const uint32_t st = sb + (c & 1) * STAGE_B;
        #pragma unroll
        for (int ks = 0; ks < 2; ks++) {
            uint32_t ah[4][4], al[4][4];
            #pragma unroll
            for (int mt = 0; mt < 4; mt++) {
                const uint32_t off = swzoff(arowb + mt * 16, achb + ks * 2);
                ldsm_x4(ah[mt], st + off);
                ldsm_x4(al[mt], st + OFF_AL + off);
            }
            #pragma unroll
            for (int p = 0; p < 4; p++) {
                uint32_t bh[4];
                const uint32_t off = swzoff(browb + p * 16, bchb + ks * 2);
                ldsm_x4(bh, st + OFF_BH + off);
                #pragma unroll
                for (int mt = 0; mt < 4; mt++) {
                    #pragma unroll
                    for (int h = 0; h < 2; h++) {
                        const int nt = p * 2 + h;
                        mma16816(acc[mt][nt], ah[mt], &bh[h * 2]);
                        mma16816(acc[mt][nt], al[mt], &bh[h * 2]);
                    }
                }
            }
        }
        __syncthreads();
    }

    // ---------------- epilogue ----------------
    const int r4 = lane >> 2;
    const int c2 = (lane & 3) * 2;
    const int colb = n0 + warpN * 64 + c2;

    #pragma unroll
    for (int mt = 0; mt < 4; mt++) {
        #pragma unroll
        for (int rh = 0; rh < 2; rh++) {
            const int row = m0 + warpM * 64 + mt * 16 + rh * 8 + r4;
            if (EPI == EPI_QK || EPI == EPI_CTX) {
                const size_t rowbase = oOff + (size_t)row * ldo + colb;
                #pragma unroll
                for (int nt = 0; nt < 8; nt++) {
                    const int col = colb + nt * 8;
                    float v0 = acc[mt][nt][rh * 2 + 0];
                    float v1 = acc[mt][nt][rh * 2 + 1];
                    if (EPI == EPI_QK) { v0 += bias[col]; v1 += bias[col + 1]; }
                    unsigned short h0, l0, h1, l1;
                    split2h(v0, h0, l0);
                    split2h(v1, h1, l1);
                    uint32_t ph = (uint32_t)h0 | ((uint32_t)h1 << 16);
                    uint32_t pl = (uint32_t)l0 | ((uint32_t)l1 << 16);
                    *(uint32_t*)(oh + rowbase + nt * 8) = ph;
                    *(uint32_t*)(ol + rowbase + nt * 8) = pl;
                }
            } else if (EPI == EPI_VT) {
                #pragma unroll
                for (int nt = 0; nt < 8; nt++) {
                    const int col = colb + nt * 8;
                    float v0 = acc[mt][nt][rh * 2 + 0] + bias[col];
                    float v1 = acc[mt][nt][rh * 2 + 1] + bias[col + 1];
                    hf h0 = __float2half_rn(v0);
                    hf h1 = __float2half_rn(v1);
                    const size_t i0 = oOff + (size_t)col * SLK + row;
                    oh[i0] = h0;
                    oh[i0 + SLK] = h1;
                }
            } else if (EPI == EPI_SC) {
                const float scale = 0.044194173824159216f;  // 1/sqrt(512)
                const size_t rowbase = oOff + (size_t)row * SLK + colb;
                const int* mp = mask + mOff + (size_t)row * SLK + colb;
                #pragma unroll
                for (int nt = 0; nt < 8; nt++) {
                    int2 mk = *(const int2*)(mp + nt * 8);
                    float2 o;
                    o.x = mk.x ? acc[mt][nt][rh * 2 + 0] * scale : -1e30f;
                    o.y = mk.y ? acc[mt][nt][rh * 2 + 1] * scale : -1e30f;
                    *(float2*)(outf + rowbase + nt * 8) = o;
                }
            } else {  // EPI_OUT
                const size_t rowbase = (size_t)row * ldo + colb;
                #pragma unroll
                for (int nt = 0; nt < 8; nt++) {
                    const int col = colb + nt * 8;
                    float2 o;
                    o.x = acc[mt][nt][rh * 2 + 0] + bias[col];
                    o.y = acc[mt][nt][rh * 2 + 1] + bias[col + 1];
                    *(float2*)(outf + rowbase + nt * 8) = o;
                }
            }
        }
    }
}

// ---------------- fused fp32 -> fp16 conversion (split for activations, single for weights) ----------------
__global__ void cvt_all(
    const float* __restrict__ x, const float* __restrict__ st,
    const float* __restrict__ wq, const float* __restrict__ wk,
    const float* __restrict__ wv, const float* __restrict__ wp,
    hf* xh, hf* xl, hf* shh, hf* sll,
    hf* wq1, hf* wk1, hf* wv1, hf* wp1)
{
    const int which = blockIdx.y;
    const float* s; hf *hi, *lo; int n4;
    if (which == 0)      { s = x;  hi = xh;  lo = xl;  n4 = NB*SLQ*DD/4; }
    else if (which == 1) { s = st; hi = shh; lo = sll; n4 = NB*SLK*DD/4; }
    else if (which == 2) { s = wq; hi = wq1; lo = nullptr; n4 = NH*DD*DD/4; }
    else if (which == 3) { s = wk; hi = wk1; lo = nullptr; n4 = NH*DD*DD/4; }
    else if (which == 4) { s = wv; hi = wv1; lo = nullptr; n4 = NH*DD*DD/4; }
    else                 { s = wp; hi = wp1; lo = nullptr; n4 = DD*HD/4; }
    int i = blockIdx.x * blockDim.x + threadIdx.x;
    if (i >= n4) return;
    float4 v = ((const float4*)s)[i];
    if (lo) {
        uint2 vh, vl;
        unsigned short* ph = (unsigned short*)&vh;
        unsigned short* pl = (unsigned short*)&vl;
        split2h(v.x, ph[0], pl[0]);
        split2h(v.y, ph[1], pl[1]);
        split2h(v.z, ph[2], pl[2]);
        split2h(v.w, ph[3], pl[3]);
        ((uint2*)hi)[i] = vh;
        ((uint2*)lo)[i] = vl;
    } else {
        uint2 vh;
        unsigned short* ph = (unsigned short*)&vh;
        hf a = __float2half_rn(v.x), b = __float2half_rn(v.y);
        hf c = __float2half_rn(v.z), d = __float2half_rn(v.w);
        ph[0] = *(unsigned short*)&a; ph[1] = *(unsigned short*)&b;
        ph[2] = *(unsigned short*)&c; ph[3] = *(unsigned short*)&d;
        ((uint2*)hi)[i] = vh;
    }
}

// ---------------- softmax over Lk=1024, emit hi/lo fp16 ----------------
__global__ void __launch_bounds__(256) softmax_hl()
{
    const size_t row = blockIdx.x;
    const float* p = g_S + row * SLK;
    hf* ph = g_Ph + row * SLK;
    hf* pl = g_Pl + row * SLK;
    const int tid = threadIdx.x;
    const int wid = tid >> 5, lane = tid & 31;
    __shared__ float sred[8];

    float4 v = ((const float4*)p)[tid];
    float m = fmaxf(fmaxf(v.x, v.y), fmaxf(v.z, v.w));
    #pragma unroll
    for (int o = 16; o; o >>= 1) m = fmaxf(m, __shfl_xor_sync(0xffffffffu, m, o));
    if (lane == 0) sred[wid] = m;
    __syncthreads();
    float rm = sred[0];
    #pragma unroll
    for (int i = 1; i < 8; i++) rm = fmaxf(rm, sred[i]);
    __syncthreads();

    v.x = __expf(v.x - rm); v.y = __expf(v.y - rm);
    v.z = __expf(v.z - rm); v.w = __expf(v.w - rm);
    float sum = (v.x + v.y) + (v.z + v.w);
    #pragma unroll
    for (int o = 16; o; o >>= 1) sum += __shfl_xor_sync(0xffffffffu, sum, o);
    if (lane == 0) sred[wid] = sum;
    __syncthreads();
    float tot = 0.f;
    #pragma unroll
    for (int i = 0; i < 8; i++) tot += sred[i];
    const float inv = 1.0f / tot;
    v.x *= inv; v.y *= inv; v.z *= inv; v.w *= inv;

    uint2 vh, vl;
    unsigned short* qh = (unsigned short*)&vh;
    unsigned short* ql = (unsigned short*)&vl;
    split2h(v.x, qh[0], ql[0]);
    split2h(v.y, qh[1], ql[1]);
    split2h(v.z, qh[2], ql[2]);
    split2h(v.w, qh[3], ql[3]);
    ((uint2*)ph)[tid] = vh;
    ((uint2*)pl)[tid] = vl;
}

// ---------------- host launch ----------------
template<typename T>
static T* symaddr(const void* sym) {
    void* p = nullptr;
    cudaGetSymbolAddress(&p, sym);
    return (T*)p;
}

extern "C" void kernel_launch(void* const* d_in, const int* in_sizes, int n_in,
                              void* d_out, int out_size)
{
    const float* x      = (const float*)d_in[0];
    const float* states = (const float*)d_in[1];
    const int*   mask   = (const int*)  d_in[2];
    const float* Wq     = (const float*)d_in[3];
    const float* bq     = (const float*)d_in[4];
    const float* Wk     = (const float*)d_in[5];
    const float* bk     = (const float*)d_in[6];
    const float* Wv     = (const float*)d_in[7];
    const float* bv     = (const float*)d_in[8];
    const float* Wp     = (const float*)d_in[9];
    const float* bp     = (const float*)d_in[10];
    float* out = (float*)d_out;

    hf *xh = symaddr<hf>(g_xh), *xl = symaddr<hf>(g_xl);
    hf *sh = symaddr<hf>(g_sh), *sl = symaddr<hf>(g_sl);
    hf *wq1 = symaddr<hf>(g_Wq);
    hf *wk1 = symaddr<hf>(g_Wk);
    hf *wv1 = symaddr<hf>(g_Wv);
    hf *wp1 = symaddr<hf>(g_Wp);
    hf *qkh = symaddr<hf>(g_QKh), *qkl = symaddr<hf>(g_QKl);
    hf *vt1 = symaddr<hf>(g_VT);
    float *Sf = symaddr<float>(g_S);
    hf *phh = symaddr<hf>(g_Ph), *pll = symaddr<hf>(g_Pl);
    hf *chh = symaddr<hf>(g_Ch), *cll = symaddr<hf>(g_Cl);

    cudaFuncSetAttribute((const void*)gemm2<EPI_QK>,  cudaFuncAttributeMaxDynamicSharedMemorySize, GEMM_SMEM);
    cudaFuncSetAttribute((const void*)gemm2<EPI_VT>,  cudaFuncAttributeMaxDynamicSharedMemorySize, GEMM_SMEM);
    cudaFuncSetAttribute((const void*)gemm2<EPI_SC>,  cudaFuncAttributeMaxDynamicSharedMemorySize, GEMM_SMEM);
    cudaFuncSetAttribute((const void*)gemm2<EPI_CTX>, cudaFuncAttributeMaxDynamicSharedMemorySize, GEMM_SMEM);
    cudaFuncSetAttribute((const void*)gemm2<EPI_OUT>, cudaFuncAttributeMaxDynamicSharedMemorySize, GEMM_SMEM);

    // Launch 0: all conversions in one grid (activations split, weights single)
    cvt_all<<<dim3(4096, 6), 256>>>(x, states, Wq, Wk, Wv, Wp,
        xh, xl, sh, sl, wq1, wk1, wv1, wp1);

    // Launch 1: Q (z<64) and K (z>=64) projections, 2-product (W single)
    gemm2<EPI_QK><<<dim3(4, 4, 128), 256, GEMM_SMEM>>>(
        xh, xl, sh, sl, DD, wq1, wk1, DD, DD,
        bq, bk, nullptr, nullptr, qkh, qkl, DD);

    // Launch 2: V projection -> V^T, 2-product, single-plane output
    gemm2<EPI_VT><<<dim3(4, 4, 64), 256, GEMM_SMEM>>>(
        sh, sl, nullptr, nullptr, DD, wv1, nullptr, DD, DD,
        bv, nullptr, nullptr, nullptr, vt1, nullptr, SLK);

    // Launch 3: scores = Q K^T * scale, masked (Q split, K hi-plane single)
    gemm2<EPI_SC><<<dim3(8, 4, 64), 256, GEMM_SMEM>>>(
        qkh, qkl, nullptr, nullptr, DD,
        qkh + (size_t)64 * SLQ * DD, nullptr, DD, DD,
        nullptr, nullptr, mask, Sf, nullptr, nullptr, SLK);

    // Launch 4: softmax + split
    softmax_hl<<<65536, 256>>>();

    // Launch 5 (profiled): ctx = P V (P split, V^T single)
    gemm2<EPI_CTX><<<dim3(4, 4, 64), 256, GEMM_SMEM>>>(
        phh, pll, nullptr, nullptr, SLK, vt1, nullptr, SLK, SLK,
        nullptr, nullptr, nullptr, nullptr, chh, cll, HD);

    // Launch 6: out = C Wp^T + bp (C split, Wp single)
    gemm2<EPI_OUT><<<dim3(4, 32, 1), 256, GEMM_SMEM>>>(
        chh, cll, nullptr, nullptr, HD, wp1, nullptr, HD, HD,
        bp, nullptr, nullptr, out, nullptr, nullptr, DD);
}

// round 11
// speedup vs baseline: 4.6461x; 1.1769x over previous
#include <cuda_runtime.h>
#include <cuda_fp16.h>
#include <cstdint>

// Problem dims
#define NB 8
#define NH 8
#define SLQ 1024
#define SLK 1024
#define DD 512
#define HD 4096

using hf = __half;

// ---------------- device global scratch ----------------
__device__ hf g_xh[(size_t)NB*SLQ*DD],  g_xl[(size_t)NB*SLQ*DD];
__device__ hf g_sh[(size_t)NB*SLK*DD],  g_sl[(size_t)NB*SLK*DD];
__device__ hf g_Wq[(size_t)NH*DD*DD];
__device__ hf g_Wk[(size_t)NH*DD*DD];
__device__ hf g_Wv[(size_t)NH*DD*DD];
__device__ hf g_Wp[(size_t)DD*HD];
__device__ hf g_QKh[(size_t)128*SLQ*DD], g_QKl[(size_t)128*SLQ*DD];  // Q: z<64, K: z>=64
__device__ hf g_VT[(size_t)64*DD*SLK];
__device__ float g_S[(size_t)64*SLQ*SLK];
__device__ hf g_P[(size_t)64*SLQ*SLK];     // single-plane P
__device__ hf g_C[(size_t)NB*SLQ*HD];      // single-plane ctx

// ---------------- PTX helpers (baseline ISA only) ----------------
__device__ __forceinline__ uint32_t smem_u32(const void* p) {
    uint32_t a;
    asm("{ .reg .u64 t; cvta.to.shared.u64 t, %1; cvt.u32.u64 %0, t; }" : "=r"(a) : "l"(p));
    return a;
}
#define CP_ASYNC16(dst, src) \
    asm volatile("cp.async.cg.shared.global [%0], [%1], 16;" :: "r"(dst), "l"(src))
#define CP_COMMIT() asm volatile("cp.async.commit_group;" ::: "memory")
#define CP_WAIT1() asm volatile("cp.async.wait_group 1;" ::: "memory")
#define CP_WAIT0() asm volatile("cp.async.wait_group 0;" ::: "memory")

__device__ __forceinline__ void ldsm_x4(uint32_t* r, uint32_t addr) {
    asm volatile("ldmatrix.sync.aligned.m8n8.x4.shared.b16 {%0,%1,%2,%3}, [%4];"
        : "=r"(r[0]), "=r"(r[1]), "=r"(r[2]), "=r"(r[3]) : "r"(addr));
}
__device__ __forceinline__ void mma16816(float* d, const uint32_t* a, const uint32_t* b) {
    asm volatile("mma.sync.aligned.m16n8k16.row.col.f32.f16.f16.f32 "
        "{%0,%1,%2,%3}, {%4,%5,%6,%7}, {%8,%9}, {%0,%1,%2,%3};"
        : "+f"(d[0]), "+f"(d[1]), "+f"(d[2]), "+f"(d[3])
        : "r"(a[0]), "r"(a[1]), "r"(a[2]), "r"(a[3]), "r"(b[0]), "r"(b[1]));
}

// 64B-row swizzle: slot' = chunk ^ ((row>>1)&3), conflict-free for ldmatrix groups
__device__ __forceinline__ uint32_t swzoff(int row, int chunk) {
    return (uint32_t)row * 64u + (uint32_t)((chunk ^ ((row >> 1) & 3)) << 4);
}

// fp16 two-digit split
__device__ __forceinline__ void split2h(float v, unsigned short& h, unsigned short& l) {
    hf h0 = __float2half_rn(v);
    hf l0 = __float2half_rn(v - __half2float(h0));
    h = *(unsigned short*)&h0;
    l = *(unsigned short*)&l0;
}

// Tiles: CTA 256(M) x 128(N) x 32(K); warps 4x2 of 64x64 (proven schedule)
// SMEM stage: Ah 16K | Al 16K | Bh 8K = 48KB slot; 2 stages = 96KB
#define OFF_AL 16384
#define OFF_BH 32768
#define STAGE_B 49152
#define GEMM_SMEM 98304

// Epilogue IDs
#define EPI_QK  0  // dual-source, bias + split hi/lo, row-major
#define EPI_VT  1  // bias + single fp16, transposed (write V^T)
#define EPI_SC  2  // scale + mask -> fp32
#define EPI_CTX 3  // single fp16, row-major (head-concat via oOff)
#define EPI_OUT 4  // bias -> fp32

// NPROD=2: D = Ahi*B + Alo*B ; NPROD=1: D = A*B (Al plane unused)
template<int EPI, int NPROD>
__global__ void __launch_bounds__(256, 1) gemm2(
    const hf* __restrict__ Ah, const hf* __restrict__ Al,
    const hf* __restrict__ A2h, const hf* __restrict__ A2l, int lda,
    const hf* __restrict__ Bh, const hf* __restrict__ B2h, int ldb,
    int Ktot,
    const float* __restrict__ bias, const float* __restrict__ bias2,
    const int* __restrict__ mask,
    float* __restrict__ outf,
    hf* __restrict__ oh, hf* __restrict__ ol, int ldo)
{
    extern __shared__ char smem[];
    const uint32_t sb = smem_u32(smem);
    const int tid = threadIdx.x;
    const int wid = tid >> 5;
    const int lane = tid & 31;
    const int z = blockIdx.z;
    const int m0 = blockIdx.y * 256;
    const int n0 = blockIdx.x * 128;

    size_t aOff = 0, bOff = 0, oOff = 0, mOff = 0;
    if (EPI == EPI_QK) {
        const int zz = z & 63;
        if (z >= 64) { Ah = A2h; Al = A2l; Bh = B2h; bias = bias2; }
        aOff = (size_t)(zz >> 3) * SLQ * DD;
        bOff = (size_t)(zz & 7) * DD * DD;
        oOff = (size_t)z * SLQ * DD;
    } else if (EPI == EPI_VT) {
        aOff = (size_t)(z >> 3) * SLQ * DD;
        bOff = (size_t)(z & 7) * DD * DD;
        oOff = (size_t)z * DD * SLK;
    } else if (EPI == EPI_SC) {
        aOff = (size_t)z * SLQ * DD;
        bOff = (size_t)z * SLK * DD;
        oOff = (size_t)z * SLQ * SLK;
        mOff = (size_t)(z >> 3) * SLQ * SLK;
    } else if (EPI == EPI_CTX) {
        aOff = (size_t)z * SLQ * SLK;
        bOff = (size_t)z * DD * SLK;
        oOff = (size_t)(z >> 3) * SLQ * HD + (size_t)(z & 7) * DD;
    }

    // ---- loader mapping: 256 threads; A: 4 row-passes, B: 2
    const int lc = tid & 3;     // 16B k-chunk (0..3)
    const int lr = tid >> 2;    // row 0..63
    uint32_t soff[4];
    #pragma unroll
    for (int i = 0; i < 4; i++)
        soff[i] = swzoff(lr + 64 * i, lc);
    const hf* sAh = Ah + aOff + (size_t)(m0 + lr) * lda + lc * 8;
    const hf* sAl = (NPROD == 2) ? (Al + aOff + (size_t)(m0 + lr) * lda + lc * 8) : nullptr;
    const hf* sBh = Bh + bOff + (size_t)(n0 + lr) * ldb + lc * 8;

    const int NCH = Ktot >> 5;  // BK = 32

#define LOAD_CHUNK(stg, kt) do { \
    const uint32_t _b = sb + (stg) * STAGE_B; \
    _Pragma("unroll") \
    for (int i = 0; i < 4; i++) CP_ASYNC16(_b + soff[i],          sAh + (kt) + (size_t)(64 * i) * lda); \
    if (NPROD == 2) { \
        _Pragma("unroll") \
        for (int i = 0; i < 4; i++) CP_ASYNC16(_b + OFF_AL + soff[i], sAl + (kt) + (size_t)(64 * i) * lda); \
    } \
    _Pragma("unroll") \
    for (int i = 0; i < 2; i++) CP_ASYNC16(_b + OFF_BH + soff[i], sBh + (kt) + (size_t)(64 * i) * ldb); \
    CP_COMMIT(); } while (0)

    LOAD_CHUNK(0, 0);

    // ---- compute mapping: warp grid 4(M) x 2(N), warp tile 64x64
    const int warpM = wid >> 1;
    const int warpN = wid & 1;
    const int grp = lane >> 3;
    const int l7  = lane & 7;
    const int arowb = warpM * 64 + ((grp & 1) << 3) + l7;   // + mt*16
    const int achb  = grp >> 1;                              // + ks*2
    const int browb = warpN * 64 + ((grp >> 1) << 3) + l7;  // + p*16
    const int bchb  = grp & 1;                               // + ks*2

    float acc[4][8][4];
    #pragma unroll
    for (int mt = 0; mt < 4; mt++)
        #pragma unroll
        for (int nt = 0; nt < 8; nt++)
            #pragma unroll
            for (int j = 0; j < 4; j++) acc[mt][nt][j] = 0.f;

    for (int c = 0; c < NCH; c++) {
        if (c + 1 < NCH) {
            LOAD_CHUNK((c + 1) & 1, (size_t)(c + 1) * 32);
            CP_WAIT1();
        } else {
            CP_WAIT0();
        }
        __syncthreads();

        const uint32_t st = sb + (c & 1) * STAGE_B;
        #pragma unroll
        for (int ks = 0; ks < 2; ks++) {
            uint32_t ah[4][4], al[4][4];
            #pragma unroll
            for (int mt = 0; mt < 4; mt++) {
                const uint32_t off = swzoff(arowb + mt * 16, achb + ks * 2);
                ldsm_x4(ah[mt], st + off);
                if (NPROD == 2) ldsm_x4(al[mt], st + OFF_AL + off);
            }
            #pragma unroll
            for (int p = 0; p < 4; p++) {
                uint32_t bh[4];
                const uint32_t off = swzoff(browb + p * 16, bchb + ks * 2);
                ldsm_x4(bh, st + OFF_BH + off);
                #pragma unroll
                for (int mt = 0; mt < 4; mt++) {
                    #pragma unroll
                    for (int h = 0; h < 2; h++) {
                        const int nt = p * 2 + h;
                        mma16816(acc[mt][nt], ah[mt], &bh[h * 2]);
                        if (NPROD == 2) mma16816(acc[mt][nt], al[mt], &bh[h * 2]);
                    }
                }
            }
        }
        __syncthreads();
    }

    // ---------------- epilogue ----------------
    const int r4 = lane >> 2;
    const int c2 = (lane & 3) * 2;
    const int colb = n0 + warpN * 64 + c2;

    #pragma unroll
    for (int mt = 0; mt < 4; mt++) {
        #pragma unroll
        for (int rh = 0; rh < 2; rh++) {
            const int row = m0 + warpM * 64 + mt * 16 + rh * 8 + r4;
            if (EPI == EPI_QK) {
                const size_t rowbase = oOff + (size_t)row * ldo + colb;
                #pragma unroll
                for (int nt = 0; nt < 8; nt++) {
                    const int col = colb + nt * 8;
                    float v0 = acc[mt][nt][rh * 2 + 0] + bias[col];
                    float v1 = acc[mt][nt][rh * 2 + 1] + bias[col + 1];
                    unsigned short h0, l0, h1, l1;
                    split2h(v0, h0, l0);
                    split2h(v1, h1, l1);
                    uint32_t ph = (uint32_t)h0 | ((uint32_t)h1 << 16);
                    uint32_t pl = (uint32_t)l0 | ((uint32_t)l1 << 16);
                    *(uint32_t*)(oh + rowbase + nt * 8) = ph;
                    *(uint32_t*)(ol + rowbase + nt * 8) = pl;
                }
            } else if (EPI == EPI_CTX) {
                const size_t rowbase = oOff + (size_t)row * ldo + colb;
                #pragma unroll
                for (int nt = 0; nt < 8; nt++) {
                    hf h0 = __float2half_rn(acc[mt][nt][rh * 2 + 0]);
                    hf h1 = __float2half_rn(acc[mt][nt][rh * 2 + 1]);
                    uint32_t ph = (uint32_t)*(unsigned short*)&h0 | ((uint32_t)*(unsigned short*)&h1 << 16);
                    *(uint32_t*)(oh + rowbase + nt * 8) = ph;
                }
            } else if (EPI == EPI_VT) {
                #pragma unroll
                for (int nt = 0; nt < 8; nt++) {
                    const int col = colb + nt * 8;
                    float v0 = acc[mt][nt][rh * 2 + 0] + bias[col];
                    float v1 = acc[mt][nt][rh * 2 + 1] + bias[col + 1];
                    const size_t i0 = oOff + (size_t)col * SLK + row;
                    oh[i0] = __float2half_rn(v0);
                    oh[i0 + SLK] = __float2half_rn(v1);
                }
            } else if (EPI == EPI_SC) {
                const float scale = 0.044194173824159216f;  // 1/sqrt(512)
                const size_t rowbase = oOff + (size_t)row * SLK + colb;
                const int* mp = mask + mOff + (size_t)row * SLK + colb;
                #pragma unroll
                for (int nt = 0; nt < 8; nt++) {
                    int2 mk = *(const int2*)(mp + nt * 8);
                    float2 o;
                    o.x = mk.x ? acc[mt][nt][rh * 2 + 0] * scale : -1e30f;
                    o.y = mk.y ? acc[mt][nt][rh * 2 + 1] * scale : -1e30f;
                    *(float2*)(outf + rowbase + nt * 8) = o;
                }
            } else {  // EPI_OUT
                const size_t rowbase = (size_t)row * ldo + colb;
                #pragma unroll
                for (int nt = 0; nt < 8; nt++) {
                    const int col = colb + nt * 8;
                    float2 o;
                    o.x = acc[mt][nt][rh * 2 + 0] + bias[col];
                    o.y = acc[mt][nt][rh * 2 + 1] + bias[col + 1];
                    *(float2*)(outf + rowbase + nt * 8) = o;
                }
            }
        }
    }
}

// ---------------- fused fp32 -> fp16 conversion (split activations, single weights) ----------------
__global__ void cvt_all(
    const float* __restrict__ x, const float* __restrict__ st,
    const float* __restrict__ wq, const float* __restrict__ wk,
    const float* __restrict__ wv, const float* __restrict__ wp,
    hf* xh, hf* xl, hf* shh, hf* sll,
    hf* wq1, hf* wk1, hf* wv1, hf* wp1)
{
    const int which = blockIdx.y;
    const float* s; hf *hi, *lo; int n4;
    if (which == 0)      { s = x;  hi = xh;  lo = xl;  n4 = NB*SLQ*DD/4; }
    else if (which == 1) { s = st; hi = shh; lo = sll; n4 = NB*SLK*DD/4; }
    else if (which == 2) { s = wq; hi = wq1; lo = nullptr; n4 = NH*DD*DD/4; }
    else if (which == 3) { s = wk; hi = wk1; lo = nullptr; n4 = NH*DD*DD/4; }
    else if (which == 4) { s = wv; hi = wv1; lo = nullptr; n4 = NH*DD*DD/4; }
    else                 { s = wp; hi = wp1; lo = nullptr; n4 = DD*HD/4; }
    int i = blockIdx.x * blockDim.x + threadIdx.x;
    if (i >= n4) return;
    float4 v = ((const float4*)s)[i];
    if (lo) {
        uint2 vh, vl;
        unsigned short* ph = (unsigned short*)&vh;
        unsigned short* pl = (unsigned short*)&vl;
        split2h(v.x, ph[0], pl[0]);
        split2h(v.y, ph[1], pl[1]);
        split2h(v.z, ph[2], pl[2]);
        split2h(v.w, ph[3], pl[3]);
        ((uint2*)hi)[i] = vh;
        ((uint2*)lo)[i] = vl;
    } else {
        uint2 vh;
        unsigned short* ph = (unsigned short*)&vh;
        hf a = __float2half_rn(v.x), b = __float2half_rn(v.y);
        hf c = __float2half_rn(v.z), d = __float2half_rn(v.w);
        ph[0] = *(unsigned short*)&a; ph[1] = *(unsigned short*)&b;
        ph[2] = *(unsigned short*)&c; ph[3] = *(unsigned short*)&d;
        ((uint2*)hi)[i] = vh;
    }
}

// ---------------- softmax over Lk=1024, emit single-plane fp16 ----------------
__global__ void __launch_bounds__(256) softmax_hl()
{
    const size_t row = blockIdx.x;
    const float* p = g_S + row * SLK;
    hf* ph = g_P + row * SLK;
    const int tid = threadIdx.x;
    const int wid = tid >> 5, lane = tid & 31;
    __shared__ float sred[8];

    float4 v = ((const float4*)p)[tid];
    float m = fmaxf(fmaxf(v.x, v.y), fmaxf(v.z, v.w));
    #pragma unroll
    for (int o = 16; o; o >>= 1) m = fmaxf(m, __shfl_xor_sync(0xffffffffu, m, o));
    if (lane == 0) sred[wid] = m;
    __syncthreads();
    float rm = sred[0];
    #pragma unroll
    for (int i = 1; i < 8; i++) rm = fmaxf(rm, sred[i]);
    __syncthreads();

    v.x = __expf(v.x - rm); v.y = __expf(v.y - rm);
    v.z = __expf(v.z - rm); v.w = __expf(v.w - rm);
    float sum = (v.x + v.y) + (v.z + v.w);
    #pragma unroll
    for (int o = 16; o; o >>= 1) sum += __shfl_xor_sync(0xffffffffu, sum, o);
    if (lane == 0) sred[wid] = sum;
    __syncthreads();
    float tot = 0.f;
    #pragma unroll
    for (int i = 0; i < 8; i++) tot += sred[i];
    const float inv = 1.0f / tot;

    uint2 vh;
    unsigned short* qh = (unsigned short*)&vh;
    hf a = __float2half_rn(v.x * inv), b = __float2half_rn(v.y * inv);
    hf c = __float2half_rn(v.z * inv), d = __float2half_rn(v.w * inv);
    qh[0] = *(unsigned short*)&a; qh[1] = *(unsigned short*)&b;
    qh[2] = *(unsigned short*)&c; qh[3] = *(unsigned short*)&d;
    ((uint2*)ph)[tid] = vh;
}

// ---------------- host launch ----------------
template<typename T>
static T* symaddr(const void* sym) {
    void* p = nullptr;
    cudaGetSymbolAddress(&p, sym);
    return (T*)p;
}

extern "C" void kernel_launch(void* const* d_in, const int* in_sizes, int n_in,
                              void* d_out, int out_size)
{
    const float* x      = (const float*)d_in[0];
    const float* states = (const float*)d_in[1];
    const int*   mask   = (const int*)  d_in[2];
    const float* Wq     = (const float*)d_in[3];
    const float* bq     = (const float*)d_in[4];
    const float* Wk     = (const float*)d_in[5];
    const float* bk     = (const float*)d_in[6];
    const float* Wv     = (const float*)d_in[7];
    const float* bv     = (const float*)d_in[8];
    const float* Wp     = (const float*)d_in[9];
    const float* bp     = (const float*)d_in[10];
    float* out = (float*)d_out;

    hf *xh = symaddr<hf>(g_xh), *xl = symaddr<hf>(g_xl);
    hf *sh = symaddr<hf>(g_sh), *sl = symaddr<hf>(g_sl);
    hf *wq1 = symaddr<hf>(g_Wq);
    hf *wk1 = symaddr<hf>(g_Wk);
    hf *wv1 = symaddr<hf>(g_Wv);
    hf *wp1 = symaddr<hf>(g_Wp);
    hf *qkh = symaddr<hf>(g_QKh), *qkl = symaddr<hf>(g_QKl);
    hf *vt1 = symaddr<hf>(g_VT);
    float *Sf = symaddr<float>(g_S);
    hf *p1 = symaddr<hf>(g_P);
    hf *c1 = symaddr<hf>(g_C);

    cudaFuncSetAttribute((const void*)gemm2<EPI_QK, 2>,  cudaFuncAttributeMaxDynamicSharedMemorySize, GEMM_SMEM);
    cudaFuncSetAttribute((const void*)gemm2<EPI_VT, 2>,  cudaFuncAttributeMaxDynamicSharedMemorySize, GEMM_SMEM);
    cudaFuncSetAttribute((const void*)gemm2<EPI_SC, 2>,  cudaFuncAttributeMaxDynamicSharedMemorySize, GEMM_SMEM);
    cudaFuncSetAttribute((const void*)gemm2<EPI_CTX, 1>, cudaFuncAttributeMaxDynamicSharedMemorySize, GEMM_SMEM);
    cudaFuncSetAttribute((const void*)gemm2<EPI_OUT, 1>, cudaFuncAttributeMaxDynamicSharedMemorySize, GEMM_SMEM);

    // Launch 0: all conversions in one grid (activations split, weights single)
    cvt_all<<<dim3(4096, 6), 256>>>(x, states, Wq, Wk, Wv, Wp,
        xh, xl, sh, sl, wq1, wk1, wv1, wp1);

    // Launch 1: Q (z<64) and K (z>=64) projections, 2-product (W single)
    gemm2<EPI_QK, 2><<<dim3(4, 4, 128), 256, GEMM_SMEM>>>(
        xh, xl, sh, sl, DD, wq1, wk1, DD, DD,
        bq, bk, nullptr, nullptr, qkh, qkl, DD);

    // Launch 2: V projection -> V^T, 2-product, single-plane output
    gemm2<EPI_VT, 2><<<dim3(4, 4, 64), 256, GEMM_SMEM>>>(
        sh, sl, nullptr, nullptr, DD, wv1, nullptr, DD, DD,
        bv, nullptr, nullptr, nullptr, vt1, nullptr, SLK);

    // Launch 3: scores = Q K^T * scale, masked (Q split, K hi-plane single)
    gemm2<EPI_SC, 2><<<dim3(8, 4, 64), 256, GEMM_SMEM>>>(
        qkh, qkl, nullptr, nullptr, DD,
        qkh + (size_t)64 * SLQ * DD, nullptr, DD, DD,
        nullptr, nullptr, mask, Sf, nullptr, nullptr, SLK);

    // Launch 4: softmax -> single-plane fp16 P
    softmax_hl<<<65536, 256>>>();

    // Launch 5 (profiled): ctx = P V, 1-product (P single, V^T single)
    gemm2<EPI_CTX, 1><<<dim3(4, 4, 64), 256, GEMM_SMEM>>>(
        p1, nullptr, nullptr, nullptr, SLK, vt1, nullptr, SLK, SLK,
        nullptr, nullptr, nullptr, nullptr, c1, nullptr, HD);

    // Launch 6: out = C Wp^T + bp, 1-product (C single, Wp single)
    gemm2<EPI_OUT, 1><<<dim3(4, 32, 1), 256, GEMM_SMEM>>>(
        c1, nullptr, nullptr, nullptr, HD, wp1, nullptr, HD, HD,
        bp, nullptr, nullptr, out, nullptr, nullptr, DD);
}

// round 12
// speedup vs baseline: 5.2720x; 1.1347x over previous
#include <cuda_runtime.h>
#include <cuda_fp16.h>
#include <cstdint>

// Problem dims
#define NB 8
#define NH 8
#define SLQ 1024
#define SLK 1024
#define DD 512
#define HD 4096

using hf = __half;

// ---------------- device global scratch ----------------
__device__ hf g_xh[(size_t)NB*SLQ*DD],  g_xl[(size_t)NB*SLQ*DD];
__device__ hf g_sh[(size_t)NB*SLK*DD],  g_sl[(size_t)NB*SLK*DD];
__device__ hf g_Wq[(size_t)NH*DD*DD];
__device__ hf g_Wk[(size_t)NH*DD*DD];
__device__ hf g_Wv[(size_t)NH*DD*DD];
__device__ hf g_Wp[(size_t)DD*HD];
__device__ hf g_QK[(size_t)128*SLQ*DD];    // single-plane Q (z<64), K (z>=64)
__device__ hf g_VT[(size_t)64*DD*SLK];
__device__ float g_S[(size_t)64*SLQ*SLK];
__device__ hf g_P[(size_t)64*SLQ*SLK];     // single-plane P
__device__ hf g_C[(size_t)NB*SLQ*HD];      // single-plane ctx

// ---------------- PTX helpers (baseline ISA only) ----------------
__device__ __forceinline__ uint32_t smem_u32(const void* p) {
    uint32_t a;
    asm("{ .reg .u64 t; cvta.to.shared.u64 t, %1; cvt.u32.u64 %0, t; }" : "=r"(a) : "l"(p));
    return a;
}
#define CP_ASYNC16(dst, src) \
    asm volatile("cp.async.cg.shared.global [%0], [%1], 16;" :: "r"(dst), "l"(src))
#define CP_COMMIT() asm volatile("cp.async.commit_group;" ::: "memory")
#define CP_WAIT1() asm volatile("cp.async.wait_group 1;" ::: "memory")
#define CP_WAIT0() asm volatile("cp.async.wait_group 0;" ::: "memory")

__device__ __forceinline__ void ldsm_x4(uint32_t* r, uint32_t addr) {
    asm volatile("ldmatrix.sync.aligned.m8n8.x4.shared.b16 {%0,%1,%2,%3}, [%4];"
        : "=r"(r[0]), "=r"(r[1]), "=r"(r[2]), "=r"(r[3]) : "r"(addr));
}
__device__ __forceinline__ void mma16816(float* d, const uint32_t* a, const uint32_t* b) {
    asm volatile("mma.sync.aligned.m16n8k16.row.col.f32.f16.f16.f32 "
        "{%0,%1,%2,%3}, {%4,%5,%6,%7}, {%8,%9}, {%0,%1,%2,%3};"
        : "+f"(d[0]), "+f"(d[1]), "+f"(d[2]), "+f"(d[3])
        : "r"(a[0]), "r"(a[1]), "r"(a[2]), "r"(a[3]), "r"(b[0]), "r"(b[1]));
}

// 64B-row swizzle: slot' = chunk ^ ((row>>1)&3), conflict-free for ldmatrix groups
__device__ __forceinline__ uint32_t swzoff(int row, int chunk) {
    return (uint32_t)row * 64u + (uint32_t)((chunk ^ ((row >> 1) & 3)) << 4);
}

// fp16 two-digit split
__device__ __forceinline__ void split2h(float v, unsigned short& h, unsigned short& l) {
    hf h0 = __float2half_rn(v);
    hf l0 = __float2half_rn(v - __half2float(h0));
    h = *(unsigned short*)&h0;
    l = *(unsigned short*)&l0;
}

// Tiles: CTA 256(M) x 128(N) x 32(K); warps 4x2 of 64x64 (proven schedule)
// SMEM stage: Ah 16K | Al 16K | Bh 8K = 48KB slot; 2 stages = 96KB
#define OFF_AL 16384
#define OFF_BH 32768
#define STAGE_B 49152
#define GEMM_SMEM 98304

// Epilogue IDs
#define EPI_QK  0  // dual-source, bias + single fp16, row-major
#define EPI_VT  1  // bias + single fp16, transposed (write V^T)
#define EPI_SC  2  // scale + mask -> fp32
#define EPI_CTX 3  // single fp16, row-major (head-concat via oOff)
#define EPI_OUT 4  // bias -> fp32

// NPROD=2: D = Ahi*B + Alo*B ; NPROD=1: D = A*B (Al plane unused)
template<int EPI, int NPROD>
__global__ void __launch_bounds__(256, 1) gemm2(
    const hf* __restrict__ Ah, const hf* __restrict__ Al,
    const hf* __restrict__ A2h, const hf* __restrict__ A2l, int lda,
    const hf* __restrict__ Bh, const hf* __restrict__ B2h, int ldb,
    int Ktot,
    const float* __restrict__ bias, const float* __restrict__ bias2,
    const int* __restrict__ mask,
    float* __restrict__ outf,
    hf* __restrict__ oh, int ldo)
{
    extern __shared__ char smem[];
    const uint32_t sb = smem_u32(smem);
    const int tid = threadIdx.x;
    const int wid = tid >> 5;
    const int lane = tid & 31;
    const int z = blockIdx.z;
    const int m0 = blockIdx.y * 256;
    const int n0 = blockIdx.x * 128;

    size_t aOff = 0, bOff = 0, oOff = 0, mOff = 0;
    if (EPI == EPI_QK) {
        const int zz = z & 63;
        if (z >= 64) { Ah = A2h; Al = A2l; Bh = B2h; bias = bias2; }
        aOff = (size_t)(zz >> 3) * SLQ * DD;
        bOff = (size_t)(zz & 7) * DD * DD;
        oOff = (size_t)z * SLQ * DD;
    } else if (EPI == EPI_VT) {
        aOff = (size_t)(z >> 3) * SLQ * DD;
        bOff = (size_t)(z & 7) * DD * DD;
        oOff = (size_t)z * DD * SLK;
    } else if (EPI == EPI_SC) {
        aOff = (size_t)z * SLQ * DD;
        bOff = (size_t)z * SLK * DD;
        oOff = (size_t)z * SLQ * SLK;
        mOff = (size_t)(z >> 3) * SLQ * SLK;
    } else if (EPI == EPI_CTX) {
        aOff = (size_t)z * SLQ * SLK;
        bOff = (size_t)z * DD * SLK;
        oOff = (size_t)(z >> 3) * SLQ * HD + (size_t)(z & 7) * DD;
    }

    // ---- loader mapping: 256 threads; A: 4 row-passes, B: 2
    const int lc = tid & 3;     // 16B k-chunk (0..3)
    const int lr = tid >> 2;    // row 0..63
    uint32_t soff[4];
    #pragma unroll
    for (int i = 0; i < 4; i++)
        soff[i] = swzoff(lr + 64 * i, lc);
    const hf* sAh = Ah + aOff + (size_t)(m0 + lr) * lda + lc * 8;
    const hf* sAl = (NPROD == 2) ? (Al + aOff + (size_t)(m0 + lr) * lda + lc * 8) : nullptr;
    const hf* sBh = Bh + bOff + (size_t)(n0 + lr) * ldb + lc * 8;

    const int NCH = Ktot >> 5;  // BK = 32

#define LOAD_CHUNK(stg, kt) do { \
    const uint32_t _b = sb + (stg) * STAGE_B; \
    _Pragma("unroll") \
    for (int i = 0; i < 4; i++) CP_ASYNC16(_b + soff[i],          sAh + (kt) + (size_t)(64 * i) * lda); \
    if (NPROD == 2) { \
        _Pragma("unroll") \
        for (int i = 0; i < 4; i++) CP_ASYNC16(_b + OFF_AL + soff[i], sAl + (kt) + (size_t)(64 * i) * lda); \
    } \
    _Pragma("unroll") \
    for (int i = 0; i < 2; i++) CP_ASYNC16(_b + OFF_BH + soff[i], sBh + (kt) + (size_t)(64 * i) * ldb); \
    CP_COMMIT(); } while (0)

    LOAD_CHUNK(0, 0);

    // ---- compute mapping: warp grid 4(M) x 2(N), warp tile 64x64
    const int warpM = wid >> 1;
    const int warpN = wid & 1;
    const int grp = lane >> 3;
    const int l7  = lane & 7;
    const int arowb = warpM * 64 + ((grp & 1) << 3) + l7;   // + mt*16
    const int achb  = grp >> 1;                              // + ks*2
    const int browb = warpN * 64 + ((grp >> 1) << 3) + l7;  // + p*16
    const int bchb  = grp & 1;                               // + ks*2

    float acc[4][8][4];
    #pragma unroll
    for (int mt = 0; mt < 4; mt++)
        #pragma unroll
        for (int nt = 0; nt < 8; nt++)
            #pragma unroll
            for (int j = 0; j < 4; j++) acc[mt][nt][j] = 0.f;

    for (int c = 0; c < NCH; c++) {
        if (c + 1 < NCH) {
            LOAD_CHUNK((c + 1) & 1, (size_t)(c + 1) * 32);
            CP_WAIT1();
        } else {
            CP_WAIT0();
        }
        __syncthreads();

        const uint32_t st = sb + (c & 1) * STAGE_B;
        #pragma unroll
        for (int ks = 0; ks < 2; ks++) {
            uint32_t ah[4][4], al[4][4];
            #pragma unroll
            for (int mt = 0; mt < 4; mt++) {
                const uint32_t off = swzoff(arowb + mt * 16, achb + ks * 2);
                ldsm_x4(ah[mt], st + off);
                if (NPROD == 2) ldsm_x4(al[mt], st + OFF_AL + off);
            }
            #pragma unroll
            for (int p = 0; p < 4; p++) {
                uint32_t bh[4];
                const uint32_t off = swzoff(browb + p * 16, bchb + ks * 2);
                ldsm_x4(bh, st + OFF_BH + off);
                #pragma unroll
                for (int mt = 0; mt < 4; mt++) {
                    #pragma unroll
                    for (int h = 0; h < 2; h++) {
                        const int nt = p * 2 + h;
                        mma16816(acc[mt][nt], ah[mt], &bh[h * 2]);
                        if (NPROD == 2) mma16816(acc[mt][nt], al[mt], &bh[h * 2]);
                    }
                }
            }
        }
        __syncthreads();
    }

    // ---------------- epilogue ----------------
    const int r4 = lane >> 2;
    const int c2 = (lane & 3) * 2;
    const int colb = n0 + warpN * 64 + c2;

    #pragma unroll
    for (int mt = 0; mt < 4; mt++) {
        #pragma unroll
        for (int rh = 0; rh < 2; rh++) {
            const int row = m0 + warpM * 64 + mt * 16 + rh * 8 + r4;
            if (EPI == EPI_QK || EPI == EPI_CTX) {
                const size_t rowbase = oOff + (size_t)row * ldo + colb;
                #pragma unroll
                for (int nt = 0; nt < 8; nt++) {
                    const int col = colb + nt * 8;
                    float v0 = acc[mt][nt][rh * 2 + 0];
                    float v1 = acc[mt][nt][rh * 2 + 1];
                    if (EPI == EPI_QK) { v0 += bias[col]; v1 += bias[col + 1]; }
                    hf h0 = __float2half_rn(v0);
                    hf h1 = __float2half_rn(v1);
                    uint32_t ph = (uint32_t)*(unsigned short*)&h0 | ((uint32_t)*(unsigned short*)&h1 << 16);
                    *(uint32_t*)(oh + rowbase + nt * 8) = ph;
                }
            } else if (EPI == EPI_VT) {
                #pragma unroll
                for (int nt = 0; nt < 8; nt++) {
                    const int col = colb + nt * 8;
                    float v0 = acc[mt][nt][rh * 2 + 0] + bias[col];
                    float v1 = acc[mt][nt][rh * 2 + 1] + bias[col + 1];
                    const size_t i0 = oOff + (size_t)col * SLK + row;
                    oh[i0] = __float2half_rn(v0);
                    oh[i0 + SLK] = __float2half_rn(v1);
                }
            } else if (EPI == EPI_SC) {
                const float scale = 0.044194173824159216f;  // 1/sqrt(512)
                const size_t rowbase = oOff + (size_t)row * SLK + colb;
                const int* mp = mask + mOff + (size_t)row * SLK + colb;
                #pragma unroll
                for (int nt = 0; nt < 8; nt++) {
                    int2 mk = *(const int2*)(mp + nt * 8);
                    float2 o;
                    o.x = mk.x ? acc[mt][nt][rh * 2 + 0] * scale : -1e30f;
                    o.y = mk.y ? acc[mt][nt][rh * 2 + 1] * scale : -1e30f;
                    *(float2*)(outf + rowbase + nt * 8) = o;
                }
            } else {  // EPI_OUT
                const size_t rowbase = (size_t)row * ldo + colb;
                #pragma unroll
                for (int nt = 0; nt < 8; nt++) {
                    const int col = colb + nt * 8;
                    float2 o;
                    o.x = acc[mt][nt][rh * 2 + 0] + bias[col];
                    o.y = acc[mt][nt][rh * 2 + 1] + bias[col + 1];
                    *(float2*)(outf + rowbase + nt * 8) = o;
                }
            }
        }
    }
}

// ---------------- fused fp32 -> fp16 conversion (split activations, single weights) ----------------
__global__ void cvt_all(
    const float* __restrict__ x, const float* __restrict__ st,
    const float* __restrict__ wq, const float* __restrict__ wk,
    const float* __restrict__ wv, const float* __restrict__ wp,
    hf* xh, hf* xl, hf* shh, hf* sll,
    hf* wq1, hf* wk1, hf* wv1, hf* wp1)
{
    const int which = blockIdx.y;
    const float* s; hf *hi, *lo; int n4;
    if (which == 0)      { s = x;  hi = xh;  lo = xl;  n4 = NB*SLQ*DD/4; }
    else if (which == 1) { s = st; hi = shh; lo = sll; n4 = NB*SLK*DD/4; }
    else if (which == 2) { s = wq; hi = wq1; lo = nullptr; n4 = NH*DD*DD/4; }
    else if (which == 3) { s = wk; hi = wk1; lo = nullptr; n4 = NH*DD*DD/4; }
    else if (which == 4) { s = wv; hi = wv1; lo = nullptr; n4 = NH*DD*DD/4; }
    else                 { s = wp; hi = wp1; lo = nullptr; n4 = DD*HD/4; }
    int i = blockIdx.x * blockDim.x + threadIdx.x;
    if (i >= n4) return;
    float4 v = ((const float4*)s)[i];
    if (lo) {
        uint2 vh, vl;
        unsigned short* ph = (unsigned short*)&vh;
        unsigned short* pl = (unsigned short*)&vl;
        split2h(v.x, ph[0], pl[0]);
        split2h(v.y, ph[1], pl[1]);
        split2h(v.z, ph[2], pl[2]);
        split2h(v.w, ph[3], pl[3]);
        ((uint2*)hi)[i] = vh;
        ((uint2*)lo)[i] = vl;
    } else {
        uint2 vh;
        unsigned short* ph = (unsigned short*)&vh;
        hf a = __float2half_rn(v.x), b = __float2half_rn(v.y);
        hf c = __float2half_rn(v.z), d = __float2half_rn(v.w);
        ph[0] = *(unsigned short*)&a; ph[1] = *(unsigned short*)&b;
        ph[2] = *(unsigned short*)&c; ph[3] = *(unsigned short*)&d;
        ((uint2*)hi)[i] = vh;
    }
}

// ---------------- softmax over Lk=1024, emit single-plane fp16 ----------------
__global__ void __launch_bounds__(256) softmax_hl()
{
    const size_t row = blockIdx.x;
    const float* p = g_S + row * SLK;
    hf* ph = g_P + row * SLK;
    const int tid = threadIdx.x;
    const int wid = tid >> 5, lane = tid & 31;
    __shared__ float sred[8];

    float4 v = ((const float4*)p)[tid];
    float m = fmaxf(fmaxf(v.x, v.y), fmaxf(v.z, v.w));
    #pragma unroll
    for (int o = 16; o; o >>= 1) m = fmaxf(m, __shfl_xor_sync(0xffffffffu, m, o));
    if (lane == 0) sred[wid] = m;
    __syncthreads();
    float rm = sred[0];
    #pragma unroll
    for (int i = 1; i < 8; i++) rm = fmaxf(rm, sred[i]);
    __syncthreads();

    v.x = __expf(v.x - rm); v.y = __expf(v.y - rm);
    v.z = __expf(v.z - rm); v.w = __expf(v.w - rm);
    float sum = (v.x + v.y) + (v.z + v.w);
    #pragma unroll
    for (int o = 16; o; o >>= 1) sum += __shfl_xor_sync(0xffffffffu, sum, o);
    if (lane == 0) sred[wid] = sum;
    __syncthreads();
    float tot = 0.f;
    #pragma unroll
    for (int i = 0; i < 8; i++) tot += sred[i];
    const float inv = 1.0f / tot;

    uint2 vh;
    unsigned short* qh = (unsigned short*)&vh;
    hf a = __float2half_rn(v.x * inv), b = __float2half_rn(v.y * inv);
    hf c = __float2half_rn(v.z * inv), d = __float2half_rn(v.w * inv);
    qh[0] = *(unsigned short*)&a; qh[1] = *(unsigned short*)&b;
    qh[2] = *(unsigned short*)&c; qh[3] = *(unsigned short*)&d;
    ((uint2*)ph)[tid] = vh;
}

// ---------------- host launch ----------------
template<typename T>
static T* symaddr(const void* sym) {
    void* p = nullptr;
    cudaGetSymbolAddress(&p, sym);
    return (T*)p;
}

extern "C" void kernel_launch(void* const* d_in, const int* in_sizes, int n_in,
                              void* d_out, int out_size)
{
    const float* x      = (const float*)d_in[0];
    const float* states = (const float*)d_in[1];
    const int*   mask   = (const int*)  d_in[2];
    const float* Wq     = (const float*)d_in[3];
    const float* bq     = (const float*)d_in[4];
    const float* Wk     = (const float*)d_in[5];
    const float* bk     = (const float*)d_in[6];
    const float* Wv     = (const float*)d_in[7];
    const float* bv     = (const float*)d_in[8];
    const float* Wp     = (const float*)d_in[9];
    const float* bp     = (const float*)d_in[10];
    float* out = (float*)d_out;

    hf *xh = symaddr<hf>(g_xh), *xl = symaddr<hf>(g_xl);
    hf *sh = symaddr<hf>(g_sh), *sl = symaddr<hf>(g_sl);
    hf *wq1 = symaddr<hf>(g_Wq);
    hf *wk1 = symaddr<hf>(g_Wk);
    hf *wv1 = symaddr<hf>(g_Wv);
    hf *wp1 = symaddr<hf>(g_Wp);
    hf *qk1 = symaddr<hf>(g_QK);
    hf *vt1 = symaddr<hf>(g_VT);
    float *Sf = symaddr<float>(g_S);
    hf *p1 = symaddr<hf>(g_P);
    hf *c1 = symaddr<hf>(g_C);

    cudaFuncSetAttribute((const void*)gemm2<EPI_QK, 2>,  cudaFuncAttributeMaxDynamicSharedMemorySize, GEMM_SMEM);
    cudaFuncSetAttribute((const void*)gemm2<EPI_VT, 2>,  cudaFuncAttributeMaxDynamicSharedMemorySize, GEMM_SMEM);
    cudaFuncSetAttribute((const void*)gemm2<EPI_SC, 1>,  cudaFuncAttributeMaxDynamicSharedMemorySize, GEMM_SMEM);
    cudaFuncSetAttribute((const void*)gemm2<EPI_CTX, 1>, cudaFuncAttributeMaxDynamicSharedMemorySize, GEMM_SMEM);
    cudaFuncSetAttribute((const void*)gemm2<EPI_OUT, 1>, cudaFuncAttributeMaxDynamicSharedMemorySize, GEMM_SMEM);

    // Launch 0: all conversions in one grid (activations split, weights single)
    cvt_all<<<dim3(4096, 6), 256>>>(x, states, Wq, Wk, Wv, Wp,
        xh, xl, sh, sl, wq1, wk1, wv1, wp1);

    // Launch 1: Q (z<64) and K (z>=64) projections, 2-product compute, single-plane output
    gemm2<EPI_QK, 2><<<dim3(4, 4, 128), 256, GEMM_SMEM>>>(
        xh, xl, sh, sl, DD, wq1, wk1, DD, DD,
        bq, bk, nullptr, nullptr, qk1, DD);

    // Launch 2: V projection -> V^T, 2-product compute, single-plane output
    gemm2<EPI_VT, 2><<<dim3(4, 4, 64), 256, GEMM_SMEM>>>(
        sh, sl, nullptr, nullptr, DD, wv1, nullptr, DD, DD,
        bv, nullptr, nullptr, nullptr, vt1, SLK);

    // Launch 3: scores = Q K^T * scale, masked — 1-product (Q single, K single)
    gemm2<EPI_SC, 1><<<dim3(8, 4, 64), 256, GEMM_SMEM>>>(
        qk1, nullptr, nullptr, nullptr, DD,
        qk1 + (size_t)64 * SLQ * DD, nullptr, DD, DD,
        nullptr, nullptr, mask, Sf, nullptr, SLK);

    // Launch 4: softmax -> single-plane fp16 P
    softmax_hl<<<65536, 256>>>();

    // Launch 5 (profiled): ctx = P V, 1-product
    gemm2<EPI_CTX, 1><<<dim3(4, 4, 64), 256, GEMM_SMEM>>>(
        p1, nullptr, nullptr, nullptr, SLK, vt1, nullptr, SLK, SLK,
        nullptr, nullptr, nullptr, nullptr, c1, HD);

    // Launch 6: out = C Wp^T + bp, 1-product
    gemm2<EPI_OUT, 1><<<dim3(4, 32, 1), 256, GEMM_SMEM>>>(
        c1, nullptr, nullptr, nullptr, HD, wp1, nullptr, HD, HD,
        bp, nullptr, nullptr, out, nullptr, DD);
}

// round 13
// speedup vs baseline: 6.2775x; 1.1907x over previous
#include <cuda_runtime.h>
#include <cuda_fp16.h>
#include <cstdint>

// Problem dims
#define NB 8
#define NH 8
#define SLQ 1024
#define SLK 1024
#define DD 512
#define HD 4096

using hf = __half;

// ---------------- device global scratch ----------------
__device__ hf g_x[(size_t)NB*SLQ*DD];
__device__ hf g_st[(size_t)NB*SLK*DD];
__device__ hf g_Wq[(size_t)NH*DD*DD];
__device__ hf g_Wk[(size_t)NH*DD*DD];
__device__ hf g_Wv[(size_t)NH*DD*DD];
__device__ hf g_Wp[(size_t)DD*HD];
__device__ hf g_QK[(size_t)128*SLQ*DD];    // single-plane Q (z<64), K (z>=64)
__device__ hf g_VT[(size_t)64*DD*SLK];
__device__ float g_S[(size_t)64*SLQ*SLK];
__device__ hf g_P[(size_t)64*SLQ*SLK];     // single-plane P
__device__ hf g_C[(size_t)NB*SLQ*HD];      // single-plane ctx

// ---------------- PTX helpers (baseline ISA only) ----------------
__device__ __forceinline__ uint32_t smem_u32(const void* p) {
    uint32_t a;
    asm("{ .reg .u64 t; cvta.to.shared.u64 t, %1; cvt.u32.u64 %0, t; }" : "=r"(a) : "l"(p));
    return a;
}
#define CP_ASYNC16(dst, src) \
    asm volatile("cp.async.cg.shared.global [%0], [%1], 16;" :: "r"(dst), "l"(src))
#define CP_COMMIT() asm volatile("cp.async.commit_group;" ::: "memory")
#define CP_WAIT1() asm volatile("cp.async.wait_group 1;" ::: "memory")
#define CP_WAIT0() asm volatile("cp.async.wait_group 0;" ::: "memory")

__device__ __forceinline__ void ldsm_x4(uint32_t* r, uint32_t addr) {
    asm volatile("ldmatrix.sync.aligned.m8n8.x4.shared.b16 {%0,%1,%2,%3}, [%4];"
        : "=r"(r[0]), "=r"(r[1]), "=r"(r[2]), "=r"(r[3]) : "r"(addr));
}
__device__ __forceinline__ void mma16816(float* d, const uint32_t* a, const uint32_t* b) {
    asm volatile("mma.sync.aligned.m16n8k16.row.col.f32.f16.f16.f32 "
        "{%0,%1,%2,%3}, {%4,%5,%6,%7}, {%8,%9}, {%0,%1,%2,%3};"
        : "+f"(d[0]), "+f"(d[1]), "+f"(d[2]), "+f"(d[3])
        : "r"(a[0]), "r"(a[1]), "r"(a[2]), "r"(a[3]), "r"(b[0]), "r"(b[1]));
}

// 64B-row swizzle: slot' = chunk ^ ((row>>1)&3), conflict-free for ldmatrix groups
__device__ __forceinline__ uint32_t swzoff(int row, int chunk) {
    return (uint32_t)row * 64u + (uint32_t)((chunk ^ ((row >> 1) & 3)) << 4);
}

// Tiles: CTA 256(M) x 128(N) x 32(K); warps 4x2 of 64x64 (proven schedule)
// SMEM stage (1-product): A 16K | B 8K = 24KB; 2 stages = 48KB
#define OFF_B 16384
#define STAGE_B 24576
#define GEMM_SMEM 49152

// Epilogue IDs
#define EPI_QK  0  // dual-source, bias + single fp16, row-major
#define EPI_VT  1  // bias + single fp16, transposed (write V^T)
#define EPI_SC  2  // scale + mask -> fp32
#define EPI_CTX 3  // single fp16, row-major (head-concat via oOff)
#define EPI_OUT 4  // bias -> fp32

// Uniform 1-product GEMM: D = A*B^T (A, B single fp16)
template<int EPI>
__global__ void __launch_bounds__(256, 1) gemm1(
    const hf* __restrict__ Ah, const hf* __restrict__ A2h, int lda,
    const hf* __restrict__ Bh, const hf* __restrict__ B2h, int ldb,
    int Ktot,
    const float* __restrict__ bias, const float* __restrict__ bias2,
    const int* __restrict__ mask,
    float* __restrict__ outf,
    hf* __restrict__ oh, int ldo)
{
    extern __shared__ char smem[];
    const uint32_t sb = smem_u32(smem);
    const int tid = threadIdx.x;
    const int wid = tid >> 5;
    const int lane = tid & 31;
    const int z = blockIdx.z;
    const int m0 = blockIdx.y * 256;
    const int n0 = blockIdx.x * 128;

    size_t aOff = 0, bOff = 0, oOff = 0, mOff = 0;
    if (EPI == EPI_QK) {
        const int zz = z & 63;
        if (z >= 64) { Ah = A2h; Bh = B2h; bias = bias2; }
        aOff = (size_t)(zz >> 3) * SLQ * DD;
        bOff = (size_t)(zz & 7) * DD * DD;
        oOff = (size_t)z * SLQ * DD;
    } else if (EPI == EPI_VT) {
        aOff = (size_t)(z >> 3) * SLQ * DD;
        bOff = (size_t)(z & 7) * DD * DD;
        oOff = (size_t)z * DD * SLK;
    } else if (EPI == EPI_SC) {
        aOff = (size_t)z * SLQ * DD;
        bOff = (size_t)z * SLK * DD;
        oOff = (size_t)z * SLQ * SLK;
        mOff = (size_t)(z >> 3) * SLQ * SLK;
    } else if (EPI == EPI_CTX) {
        aOff = (size_t)z * SLQ * SLK;
        bOff = (size_t)z * DD * SLK;
        oOff = (size_t)(z >> 3) * SLQ * HD + (size_t)(z & 7) * DD;
    }

    // ---- loader mapping: 256 threads; A: 4 row-passes, B: 2
    const int lc = tid & 3;     // 16B k-chunk (0..3)
    const int lr = tid >> 2;    // row 0..63
    uint32_t soff[4];
    #pragma unroll
    for (int i = 0; i < 4; i++)
        soff[i] = swzoff(lr + 64 * i, lc);
    const hf* sA = Ah + aOff + (size_t)(m0 + lr) * lda + lc * 8;
    const hf* sB = Bh + bOff + (size_t)(n0 + lr) * ldb + lc * 8;

    const int NCH = Ktot >> 5;  // BK = 32

#define LOAD_CHUNK(stg, kt) do { \
    const uint32_t _b = sb + (stg) * STAGE_B; \
    _Pragma("unroll") \
    for (int i = 0; i < 4; i++) CP_ASYNC16(_b + soff[i],         sA + (kt) + (size_t)(64 * i) * lda); \
    _Pragma("unroll") \
    for (int i = 0; i < 2; i++) CP_ASYNC16(_b + OFF_B + soff[i], sB + (kt) + (size_t)(64 * i) * ldb); \
    CP_COMMIT(); } while (0)

    LOAD_CHUNK(0, 0);

    // ---- compute mapping: warp grid 4(M) x 2(N), warp tile 64x64
    const int warpM = wid >> 1;
    const int warpN = wid & 1;
    const int grp = lane >> 3;
    const int l7  = lane & 7;
    const int arowb = warpM * 64 + ((grp & 1) << 3) + l7;   // + mt*16
    const int achb  = grp >> 1;                              // + ks*2
    const int browb = warpN * 64 + ((grp >> 1) << 3) + l7;  // + p*16
    const int bchb  = grp & 1;                               // + ks*2

    float acc[4][8][4];
    #pragma unroll
    for (int mt = 0; mt < 4; mt++)
        #pragma unroll
        for (int nt = 0; nt < 8; nt++)
            #pragma unroll
            for (int j = 0; j < 4; j++) acc[mt][nt][j] = 0.f;

    for (int c = 0; c < NCH; c++) {
        if (c + 1 < NCH) {
            LOAD_CHUNK((c + 1) & 1, (size_t)(c + 1) * 32);
            CP_WAIT1();
        } else {
            CP_WAIT0();
        }
        __syncthreads();

        const uint32_t st = sb + (c & 1) * STAGE_B;
        #pragma unroll
        for (int ks = 0; ks < 2; ks++) {
            uint32_t ah[4][4];
            #pragma unroll
            for (int mt = 0; mt < 4; mt++) {
                const uint32_t off = swzoff(arowb + mt * 16, achb + ks * 2);
                ldsm_x4(ah[mt], st + off);
            }
            #pragma unroll
            for (int p = 0; p < 4; p++) {
                uint32_t bh[4];
                const uint32_t off = swzoff(browb + p * 16, bchb + ks * 2);
                ldsm_x4(bh, st + OFF_B + off);
                #pragma unroll
                for (int mt = 0; mt < 4; mt++) {
                    #pragma unroll
                    for (int h = 0; h < 2; h++) {
                        mma16816(acc[mt][p * 2 + h], ah[mt], &bh[h * 2]);
                    }
                }
            }
        }
        __syncthreads();
    }

    // ---------------- epilogue ----------------
    const int r4 = lane >> 2;
    const int c2 = (lane & 3) * 2;
    const int colb = n0 + warpN * 64 + c2;

    #pragma unroll
    for (int mt = 0; mt < 4; mt++) {
        #pragma unroll
        for (int rh = 0; rh < 2; rh++) {
            const int row = m0 + warpM * 64 + mt * 16 + rh * 8 + r4;
            if (EPI == EPI_QK || EPI == EPI_CTX) {
                const size_t rowbase = oOff + (size_t)row * ldo + colb;
                #pragma unroll
                for (int nt = 0; nt < 8; nt++) {
                    const int col = colb + nt * 8;
                    float v0 = acc[mt][nt][rh * 2 + 0];
                    float v1 = acc[mt][nt][rh * 2 + 1];
                    if (EPI == EPI_QK) { v0 += bias[col]; v1 += bias[col + 1]; }
                    hf h0 = __float2half_rn(v0);
                    hf h1 = __float2half_rn(v1);
                    uint32_t ph = (uint32_t)*(unsigned short*)&h0 | ((uint32_t)*(unsigned short*)&h1 << 16);
                    *(uint32_t*)(oh + rowbase + nt * 8) = ph;
                }
            } else if (EPI == EPI_VT) {
                #pragma unroll
                for (int nt = 0; nt < 8; nt++) {
                    const int col = colb + nt * 8;
                    float v0 = acc[mt][nt][rh * 2 + 0] + bias[col];
                    float v1 = acc[mt][nt][rh * 2 + 1] + bias[col + 1];
                    const size_t i0 = oOff + (size_t)col * SLK + row;
                    oh[i0] = __float2half_rn(v0);
                    oh[i0 + SLK] = __float2half_rn(v1);
                }
            } else if (EPI == EPI_SC) {
                const float scale = 0.044194173824159216f;  // 1/sqrt(512)
                const size_t rowbase = oOff + (size_t)row * SLK + colb;
                const int* mp = mask + mOff + (size_t)row * SLK + colb;
                #pragma unroll
                for (int nt = 0; nt < 8; nt++) {
                    int2 mk = *(const int2*)(mp + nt * 8);
                    float2 o;
                    o.x = mk.x ? acc[mt][nt][rh * 2 + 0] * scale : -1e30f;
                    o.y = mk.y ? acc[mt][nt][rh * 2 + 1] * scale : -1e30f;
                    *(float2*)(outf + rowbase + nt * 8) = o;
                }
            } else {  // EPI_OUT
                const size_t rowbase = (size_t)row * ldo + colb;
                #pragma unroll
                for (int nt = 0; nt < 8; nt++) {
                    const int col = colb + nt * 8;
                    float2 o;
                    o.x = acc[mt][nt][rh * 2 + 0] + bias[col];
                    o.y = acc[mt][nt][rh * 2 + 1] + bias[col + 1];
                    *(float2*)(outf + rowbase + nt * 8) = o;
                }
            }
        }
    }
}

// ---------------- fused fp32 -> fp16 conversion (single plane, all tensors) ----------------
__global__ void cvt_all(
    const float* __restrict__ x, const float* __restrict__ st,
    const float* __restrict__ wq, const float* __restrict__ wk,
    const float* __restrict__ wv, const float* __restrict__ wp,
    hf* x1, hf* st1, hf* wq1, hf* wk1, hf* wv1, hf* wp1)
{
    const int which = blockIdx.y;
    const float* s; hf* d; int n4;
    if (which == 0)      { s = x;  d = x1;  n4 = NB*SLQ*DD/4; }
    else if (which == 1) { s = st; d = st1; n4 = NB*SLK*DD/4; }
    else if (which == 2) { s = wq; d = wq1; n4 = NH*DD*DD/4; }
    else if (which == 3) { s = wk; d = wk1; n4 = NH*DD*DD/4; }
    else if (which == 4) { s = wv; d = wv1; n4 = NH*DD*DD/4; }
    else                 { s = wp; d = wp1; n4 = DD*HD/4; }
    int i = blockIdx.x * blockDim.x + threadIdx.x;
    if (i >= n4) return;
    float4 v = ((const float4*)s)[i];
    uint2 vh;
    unsigned short* ph = (unsigned short*)&vh;
    hf a = __float2half_rn(v.x), b = __float2half_rn(v.y);
    hf c = __float2half_rn(v.z), dd = __float2half_rn(v.w);
    ph[0] = *(unsigned short*)&a; ph[1] = *(unsigned short*)&b;
    ph[2] = *(unsigned short*)&c; ph[3] = *(unsigned short*)&dd;
    ((uint2*)d)[i] = vh;
}

// ---------------- softmax over Lk=1024, emit single-plane fp16 ----------------
__global__ void __launch_bounds__(256) softmax_hl()
{
    const size_t row = blockIdx.x;
    const float* p = g_S + row * SLK;
    hf* ph = g_P + row * SLK;
    const int tid = threadIdx.x;
    const int wid = tid >> 5, lane = tid & 31;
    __shared__ float sred[8];

    float4 v = ((const float4*)p)[tid];
    float m = fmaxf(fmaxf(v.x, v.y), fmaxf(v.z, v.w));
    #pragma unroll
    for (int o = 16; o; o >>= 1) m = fmaxf(m, __shfl_xor_sync(0xffffffffu, m, o));
    if (lane == 0) sred[wid] = m;
    __syncthreads();
    float rm = sred[0];
    #pragma unroll
    for (int i = 1; i < 8; i++) rm = fmaxf(rm, sred[i]);
    __syncthreads();

    v.x = __expf(v.x - rm); v.y = __expf(v.y - rm);
    v.z = __expf(v.z - rm); v.w = __expf(v.w - rm);
    float sum = (v.x + v.y) + (v.z + v.w);
    #pragma unroll
    for (int o = 16; o; o >>= 1) sum += __shfl_xor_sync(0xffffffffu, sum, o);
    if (lane == 0) sred[wid] = sum;
    __syncthreads();
    float tot = 0.f;
    #pragma unroll
    for (int i = 0; i < 8; i++) tot += sred[i];
    const float inv = 1.0f / tot;

    uint2 vh;
    unsigned short* qh = (unsigned short*)&vh;
    hf a = __float2half_rn(v.x * inv), b = __float2half_rn(v.y * inv);
    hf c = __float2half_rn(v.z * inv), d = __float2half_rn(v.w * inv);
    qh[0] = *(unsigned short*)&a; qh[1] = *(unsigned short*)&b;
    qh[2] = *(unsigned short*)&c; qh[3] = *(unsigned short*)&d;
    ((uint2*)ph)[tid] = vh;
}

// ---------------- host launch ----------------
template<typename T>
static T* symaddr(const void* sym) {
    void* p = nullptr;
    cudaGetSymbolAddress(&p, sym);
    return (T*)p;
}

extern "C" void kernel_launch(void* const* d_in, const int* in_sizes, int n_in,
                              void* d_out, int out_size)
{
    const float* x      = (const float*)d_in[0];
    const float* states = (const float*)d_in[1];
    const int*   mask   = (const int*)  d_in[2];
    const float* Wq     = (const float*)d_in[3];
    const float* bq     = (const float*)d_in[4];
    const float* Wk     = (const float*)d_in[5];
    const float* bk     = (const float*)d_in[6];
    const float* Wv     = (const float*)d_in[7];
    const float* bv     = (const float*)d_in[8];
    const float* Wp     = (const float*)d_in[9];
    const float* bp     = (const float*)d_in[10];
    float* out = (float*)d_out;

    hf *x1 = symaddr<hf>(g_x);
    hf *st1 = symaddr<hf>(g_st);
    hf *wq1 = symaddr<hf>(g_Wq);
    hf *wk1 = symaddr<hf>(g_Wk);
    hf *wv1 = symaddr<hf>(g_Wv);
    hf *wp1 = symaddr<hf>(g_Wp);
    hf *qk1 = symaddr<hf>(g_QK);
    hf *vt1 = symaddr<hf>(g_VT);
    float *Sf = symaddr<float>(g_S);
    hf *p1 = symaddr<hf>(g_P);
    hf *c1 = symaddr<hf>(g_C);

    cudaFuncSetAttribute((const void*)gemm1<EPI_QK>,  cudaFuncAttributeMaxDynamicSharedMemorySize, GEMM_SMEM);
    cudaFuncSetAttribute((const void*)gemm1<EPI_VT>,  cudaFuncAttributeMaxDynamicSharedMemorySize, GEMM_SMEM);
    cudaFuncSetAttribute((const void*)gemm1<EPI_SC>,  cudaFuncAttributeMaxDynamicSharedMemorySize, GEMM_SMEM);
    cudaFuncSetAttribute((const void*)gemm1<EPI_CTX>, cudaFuncAttributeMaxDynamicSharedMemorySize, GEMM_SMEM);
    cudaFuncSetAttribute((const void*)gemm1<EPI_OUT>, cudaFuncAttributeMaxDynamicSharedMemorySize, GEMM_SMEM);

    // Launch 0: all conversions in one grid (single plane everywhere)
    cvt_all<<<dim3(4096, 6), 256>>>(x, states, Wq, Wk, Wv, Wp,
        x1, st1, wq1, wk1, wv1, wp1);

    // Launch 1: Q (z<64) and K (z>=64) projections, 1-product
    gemm1<EPI_QK><<<dim3(4, 4, 128), 256, GEMM_SMEM>>>(
        x1, st1, DD, wq1, wk1, DD, DD,
        bq, bk, nullptr, nullptr, qk1, DD);

    // Launch 2: V projection -> V^T, 1-product
    gemm1<EPI_VT><<<dim3(4, 4, 64), 256, GEMM_SMEM>>>(
        st1, nullptr, DD, wv1, nullptr, DD, DD,
        bv, nullptr, nullptr, nullptr, vt1, SLK);

    // Launch 3: scores = Q K^T * scale, masked — 1-product
    gemm1<EPI_SC><<<dim3(8, 4, 64), 256, GEMM_SMEM>>>(
        qk1, nullptr, DD,
        qk1 + (size_t)64 * SLQ * DD, nullptr, DD, DD,
        nullptr, nullptr, mask, Sf, nullptr, SLK);

    // Launch 4: softmax -> single-plane fp16 P
    softmax_hl<<<65536, 256>>>();

    // Launch 5 (profiled): ctx = P V, 1-product
    gemm1<EPI_CTX><<<dim3(4, 4, 64), 256, GEMM_SMEM>>>(
        p1, nullptr, SLK, vt1, nullptr, SLK, SLK,
        nullptr, nullptr, nullptr, nullptr, c1, HD);

    // Launch 6: out = C Wp^T + bp, 1-product
    gemm1<EPI_OUT><<<dim3(4, 32, 1), 256, GEMM_SMEM>>>(
        c1, nullptr, HD, wp1, nullptr, HD, HD,
        bp, nullptr, nullptr, out, nullptr, DD);
}